// round 6
// baseline (speedup 1.0000x reference)
#include <cuda_runtime.h>

#define BATCH 4
#define DD 96
#define NS 8
#define KD 4
#define LL 4096
#define CS 64     // chunk size (steps)
#define NCH 64    // number of chunks = LL/CS
#define NGRP 8    // CS/8

// ---------------- scratch (device globals; no allocation allowed) ----------------
__device__ float  g_xa [BATCH*LL*DD];
__device__ float  g_z  [BATCH*LL*DD];          // silu(z)
__device__ float  g_xc [BATCH*LL*DD];          // conv+silu output
__device__ float2 g_eu [BATCH*KD*LL*DD];       // {e1,u} ; layout [(bk*NCH+ch)*96+d]*CS + s
__device__ float  g_bB [BATCH*KD*LL*8];        // B
__device__ float  g_bC [BATCH*KD*LL*8];        // C
__device__ float  g_y  [BATCH*KD*LL*DD];       // scan output per direction
__device__ float  g_hp [BATCH*KD*NCH*16*DD];   // per-chunk {h_end(8),P(8)} comp-major [..][comp][d]
__device__ float  g_hin[BATCH*KD*NCH*8*DD];    // per-chunk incoming state comp-major
__device__ float  g_mid[BATCH*DD*LL];          // inter-block activation, planar (b,c,p)

// ---------------- K1: in-projection GEMM (planar (b,c,p) -> xa, silu(z)) --------
// grid 256 (= B * L/64), block 192. Each CTA: 64 positions, 192 output channels.
__global__ void k_inproj(const float* __restrict__ src, const float* __restrict__ in_w){
    __shared__ __align__(16) float sm[64*97];   // union: X[96][64] then OUT[64][97]
    int b  = blockIdx.x >> 6;
    int p0 = (blockIdx.x & 63) << 6;
    int t  = threadIdx.x;
    for (int i = t; i < 96*64; i += 192){
        int c = i >> 6, m = i & 63;
        sm[i] = src[((b*96 + c) << 12) + p0 + m];
    }
    __syncthreads();
    float acc[64];
    #pragma unroll
    for (int m = 0; m < 64; m++) acc[m] = 0.f;
    const float* wrow = in_w + t*96;
    for (int c = 0; c < 96; c++){
        float wv = __ldg(wrow + c);
        const float4* xr = (const float4*)(sm + (c<<6));
        #pragma unroll
        for (int m4 = 0; m4 < 16; m4++){
            float4 xv = xr[m4];
            acc[4*m4+0] = fmaf(wv, xv.x, acc[4*m4+0]);
            acc[4*m4+1] = fmaf(wv, xv.y, acc[4*m4+1]);
            acc[4*m4+2] = fmaf(wv, xv.z, acc[4*m4+2]);
            acc[4*m4+3] = fmaf(wv, xv.w, acc[4*m4+3]);
        }
    }
    __syncthreads();
    if (t < 96){
        #pragma unroll
        for (int m = 0; m < 64; m++) sm[m*97 + t] = acc[m];
    }
    __syncthreads();
    for (int i = t; i < 64*96; i += 192){
        int m = i/96, d = i - m*96;
        g_xa[(b*LL + p0 + m)*96 + d] = sm[m*97 + d];
    }
    __syncthreads();
    if (t >= 96){
        #pragma unroll
        for (int m = 0; m < 64; m++) sm[m*97 + (t-96)] = acc[m];
    }
    __syncthreads();
    for (int i = t; i < 64*96; i += 192){
        int m = i/96, d = i - m*96;
        float v = sm[m*97 + d];
        g_z[(b*LL + p0 + m)*96 + d] = v * __fdividef(1.f, 1.f + __expf(-v));
    }
}

// ---------------- K2: depthwise 3x3 conv + bias + silu ----------------
// grid 6144, block 256 : one thread per (b,p,d)
__global__ void k_conv(const float* __restrict__ cw, const float* __restrict__ cb){
    int idx = blockIdx.x*256 + threadIdx.x;
    int d  = idx % 96;
    int pp = idx / 96;
    int p  = pp & 4095, b = pp >> 12;
    int h  = p >> 6,    w = p & 63;
    const float* wt = cw + d*9;
    float a = 0.f;
    #pragma unroll
    for (int i = 0; i < 3; i++){
        int hh = h + i - 1;
        if ((unsigned)hh < 64u){
            #pragma unroll
            for (int j = 0; j < 3; j++){
                int ww = w + j - 1;
                if ((unsigned)ww < 64u)
                    a = fmaf(__ldg(wt + i*3 + j), g_xa[(b*LL + (hh<<6) + ww)*96 + d], a);
            }
        }
    }
    a += __ldg(cb + d);
    g_xc[idx] = a * __fdividef(1.f, 1.f + __expf(-a));
}

// direction index map: scan step l of direction k reads spatial position perm(k,l)
__device__ __forceinline__ int perm_idx(int k, int l){
    if (k == 0) return l;
    if (k == 1) return ((l & 63) << 6) | (l >> 6);
    if (k == 2) return 4095 - l;
    int m = 4095 - l; return ((m & 63) << 6) | (m >> 6);
}

// ---------------- K3: x-projection + dt + softplus precompute ----------------
// grid 2048 (= B*K * L/32), block 256
__global__ void __launch_bounds__(256) k_xproj(const float* __restrict__ xpw,
                        const float* __restrict__ dtw, const float* __restrict__ dtb){
    __shared__ __align__(16) float xvS[32*100];
    __shared__ float xdbl[32*25];
    __shared__ __align__(16) float xpS[22*96];
    __shared__ float dtwS[96*6];
    __shared__ float dtbS[96];
    int t   = threadIdx.x;
    int g   = blockIdx.x;
    int seg = g & 127, bk = g >> 7;
    int b   = bk >> 2,  k = bk & 3;
    int l0  = seg << 5;
    for (int i = t; i < 22*96; i += 256) xpS[i]  = xpw[k*22*96 + i];
    for (int i = t; i < 96*6;  i += 256) dtwS[i] = dtw[k*96*6 + i];
    if (t < 96) dtbS[t] = dtb[k*96 + t];
    for (int i = t; i < 32*96; i += 256){
        int m = i/96, d = i - m*96;
        int p = perm_idx(k, l0 + m);
        xvS[m*100 + d] = g_xc[(b*LL + p)*96 + d];
    }
    __syncthreads();
    for (int j = t; j < 704; j += 256){
        int m = j/22, c = j - m*22;
        const float4* a4 = (const float4*)(xpS + c*96);
        const float4* x4 = (const float4*)(xvS + m*100);
        float acc = 0.f;
        #pragma unroll
        for (int q = 0; q < 24; q++){
            float4 av = a4[q], xv = x4[q];
            acc += av.x*xv.x + av.y*xv.y + av.z*xv.z + av.w*xv.w;
        }
        xdbl[m*25 + c] = acc;
    }
    __syncthreads();
    // chunk-major eu write: chunk = seg>>1, base step = (seg&1)*32
    int chunk = seg >> 1, s0 = (seg & 1) << 5;
    for (int j = t; j < 32*96; j += 256){
        int m = j & 31, d = j >> 5;        // m fastest -> contiguous stores
        float s = dtbS[d];
        #pragma unroll
        for (int r = 0; r < 6; r++) s = fmaf(dtwS[d*6 + r], xdbl[m*25 + r], s);
        float et    = __expf(fminf(s, 60.f));
        float delta = (s > 15.f) ? s : __logf(1.f + et);   // softplus
        float e1    = __fdividef(1.f, 1.f + et);           // exp(-softplus(s))
        g_eu[((bk*NCH + chunk)*96 + d)*CS + s0 + m] = make_float2(e1, delta * xvS[m*100 + d]);
    }
    {
        int m = t >> 3, i = t & 7;   // 256 threads cover 32*8 exactly
        g_bB[(bk*LL + l0 + m)*8 + i] = xdbl[m*25 + 6 + i];
        g_bC[(bk*LL + l0 + m)*8 + i] = xdbl[m*25 + 14 + i];
    }
}

// log-depth powers e1^1..e1^8
#define POWER_TREE(e1, P)                                     \
    { P[0]=e1; P[1]=e1*e1; P[3]=P[1]*P[1]; P[2]=P[1]*e1;      \
      P[4]=P[3]*e1; P[5]=P[3]*P[1]; P[6]=P[3]*P[2]; P[7]=P[3]*P[3]; }

// ---------------- K4: scan pass 1 (per-chunk h_end and A-product) ----------------
// grid (NCH, 16), block 96
__global__ void __launch_bounds__(96) k_scan1(const float* __restrict__ alogs){
    __shared__ __align__(16) float bS[CS*8];
    int chunk = blockIdx.x, bk = blockIdx.y;
    int k = bk & 3;
    int d = threadIdx.x;
    int l0 = chunk*CS;
    for (int i = d; i < CS*8; i += 96) bS[i] = g_bB[(bk*LL + l0)*8 + i];
    float aN[8]; bool fast = true;
    const float* arow = alogs + (k*96 + d)*8;
    #pragma unroll
    for (int n = 0; n < 8; n++){
        float a = -__expf(arow[n]); aN[n] = a;
        fast = fast && (fabsf(a + (float)(n+1)) < 1e-3f*(float)(n+1));
    }
    __syncthreads();
    float h[8];
    #pragma unroll
    for (int n = 0; n < 8; n++) h[n] = 0.f;
    int base2 = ((bk*NCH + chunk)*96 + d)*CS;
    int ob = (bk*NCH + chunk)*16*96 + d;    // comp-major: +comp*96
    if (fast){
        const float4* eu4 = (const float4*)(g_eu + base2);  // 2 steps per float4
        float4 buf[4];
        #pragma unroll
        for (int i = 0; i < 4; i++) buf[i] = eu4[i];
        float q = 1.f;
        for (int grp = 0; grp < NGRP; grp++){
            float4 nxt[4];
            if (grp + 1 < NGRP){
                #pragma unroll
                for (int i = 0; i < 4; i++) nxt[i] = eu4[(grp+1)*4 + i];
            }
            #pragma unroll
            for (int i = 0; i < 4; i++){
                int s = grp*8 + i*2;
                {   float e1 = buf[i].x, u = buf[i].y;
                    float P[8]; POWER_TREE(e1, P);
                    q *= e1;
                    float4 b0 = *(const float4*)(bS + s*8);
                    float4 b1 = *(const float4*)(bS + s*8 + 4);
                    h[0]=fmaf(P[0],h[0],u*b0.x); h[1]=fmaf(P[1],h[1],u*b0.y);
                    h[2]=fmaf(P[2],h[2],u*b0.z); h[3]=fmaf(P[3],h[3],u*b0.w);
                    h[4]=fmaf(P[4],h[4],u*b1.x); h[5]=fmaf(P[5],h[5],u*b1.y);
                    h[6]=fmaf(P[6],h[6],u*b1.z); h[7]=fmaf(P[7],h[7],u*b1.w);
                }
                {   float e1 = buf[i].z, u = buf[i].w;
                    float P[8]; POWER_TREE(e1, P);
                    q *= e1;
                    float4 b0 = *(const float4*)(bS + (s+1)*8);
                    float4 b1 = *(const float4*)(bS + (s+1)*8 + 4);
                    h[0]=fmaf(P[0],h[0],u*b0.x); h[1]=fmaf(P[1],h[1],u*b0.y);
                    h[2]=fmaf(P[2],h[2],u*b0.z); h[3]=fmaf(P[3],h[3],u*b0.w);
                    h[4]=fmaf(P[4],h[4],u*b1.x); h[5]=fmaf(P[5],h[5],u*b1.y);
                    h[6]=fmaf(P[6],h[6],u*b1.z); h[7]=fmaf(P[7],h[7],u*b1.w);
                }
            }
            #pragma unroll
            for (int i = 0; i < 4; i++) buf[i] = nxt[i];
        }
        float P[8]; POWER_TREE(q, P);
        #pragma unroll
        for (int n = 0; n < 8; n++){ g_hp[ob + n*96] = h[n]; g_hp[ob + (8+n)*96] = P[n]; }
    } else {
        const float2* eu2 = g_eu + base2;
        float P[8];
        #pragma unroll
        for (int n = 0; n < 8; n++) P[n] = 1.f;
        for (int s = 0; s < CS; s++){
            float2 eu = eu2[s];
            float delta = -__logf(fmaxf(eu.x, 1e-37f));
            #pragma unroll
            for (int n = 0; n < 8; n++){
                float dA = __expf(delta*aN[n]);
                h[n] = fmaf(dA, h[n], eu.y*bS[s*8 + n]);
                P[n] *= dA;
            }
        }
        #pragma unroll
        for (int n = 0; n < 8; n++){ g_hp[ob + n*96] = h[n]; g_hp[ob + (8+n)*96] = P[n]; }
    }
}

// ---------------- K5: chunk-boundary scan (tiny, coalesced + prefetched) ----------------
__global__ void k_mid(){
    int t = blockIdx.x*128 + threadIdx.x;
    if (t >= 16*96) return;
    int bk = t/96, d = t - bk*96;
    float h[8];
    #pragma unroll
    for (int n = 0; n < 8; n++) h[n] = 0.f;
    float cur[16];
    {
        int hb = (bk*NCH)*16*96 + d;
        #pragma unroll
        for (int i = 0; i < 16; i++) cur[i] = g_hp[hb + i*96];
    }
    for (int c = 0; c < NCH; c++){
        float nxt[16];
        if (c + 1 < NCH){
            int hb = (bk*NCH + c + 1)*16*96 + d;
            #pragma unroll
            for (int i = 0; i < 16; i++) nxt[i] = g_hp[hb + i*96];
        }
        int ib = (bk*NCH + c)*8*96 + d;
        #pragma unroll
        for (int n = 0; n < 8; n++) g_hin[ib + n*96] = h[n];
        #pragma unroll
        for (int n = 0; n < 8; n++) h[n] = fmaf(cur[8+n], h[n], cur[n]);
        #pragma unroll
        for (int i = 0; i < 16; i++) cur[i] = nxt[i];
    }
}

// ---------------- K6: scan pass 2 (seeded recompute, emit y) ----------------
__global__ void __launch_bounds__(96) k_scan2(const float* __restrict__ alogs){
    __shared__ __align__(16) float bS[CS*8];
    __shared__ __align__(16) float cS[CS*8];
    int chunk = blockIdx.x, bk = blockIdx.y;
    int k = bk & 3;
    int d = threadIdx.x;
    int l0 = chunk*CS;
    for (int i = d; i < CS*8; i += 96){
        bS[i] = g_bB[(bk*LL + l0)*8 + i];
        cS[i] = g_bC[(bk*LL + l0)*8 + i];
    }
    float aN[8]; bool fast = true;
    const float* arow = alogs + (k*96 + d)*8;
    #pragma unroll
    for (int n = 0; n < 8; n++){
        float a = -__expf(arow[n]); aN[n] = a;
        fast = fast && (fabsf(a + (float)(n+1)) < 1e-3f*(float)(n+1));
    }
    float h[8];
    {
        int ib = (bk*NCH + chunk)*8*96 + d;
        #pragma unroll
        for (int n = 0; n < 8; n++) h[n] = g_hin[ib + n*96];
    }
    __syncthreads();
    int base2 = ((bk*NCH + chunk)*96 + d)*CS;
    int ybase = (bk*LL + l0)*96 + d;
    if (fast){
        const float4* eu4 = (const float4*)(g_eu + base2);
        float4 buf[4];
        #pragma unroll
        for (int i = 0; i < 4; i++) buf[i] = eu4[i];
        for (int grp = 0; grp < NGRP; grp++){
            float4 nxt[4];
            if (grp + 1 < NGRP){
                #pragma unroll
                for (int i = 0; i < 4; i++) nxt[i] = eu4[(grp+1)*4 + i];
            }
            #pragma unroll
            for (int i = 0; i < 4; i++){
                int s = grp*8 + i*2;
                {   float e1 = buf[i].x, u = buf[i].y;
                    float P[8]; POWER_TREE(e1, P);
                    float4 b0 = *(const float4*)(bS + s*8);
                    float4 b1 = *(const float4*)(bS + s*8 + 4);
                    h[0]=fmaf(P[0],h[0],u*b0.x); h[1]=fmaf(P[1],h[1],u*b0.y);
                    h[2]=fmaf(P[2],h[2],u*b0.z); h[3]=fmaf(P[3],h[3],u*b0.w);
                    h[4]=fmaf(P[4],h[4],u*b1.x); h[5]=fmaf(P[5],h[5],u*b1.y);
                    h[6]=fmaf(P[6],h[6],u*b1.z); h[7]=fmaf(P[7],h[7],u*b1.w);
                    float4 c0 = *(const float4*)(cS + s*8);
                    float4 c1 = *(const float4*)(cS + s*8 + 4);
                    float a0 = h[0]*c0.x, a1 = h[1]*c0.y;
                    a0 = fmaf(h[2], c0.z, a0);  a1 = fmaf(h[3], c0.w, a1);
                    a0 = fmaf(h[4], c1.x, a0);  a1 = fmaf(h[5], c1.y, a1);
                    a0 = fmaf(h[6], c1.z, a0);  a1 = fmaf(h[7], c1.w, a1);
                    g_y[ybase + s*96] = a0 + a1;
                }
                {   float e1 = buf[i].z, u = buf[i].w;
                    float P[8]; POWER_TREE(e1, P);
                    float4 b0 = *(const float4*)(bS + (s+1)*8);
                    float4 b1 = *(const float4*)(bS + (s+1)*8 + 4);
                    h[0]=fmaf(P[0],h[0],u*b0.x); h[1]=fmaf(P[1],h[1],u*b0.y);
                    h[2]=fmaf(P[2],h[2],u*b0.z); h[3]=fmaf(P[3],h[3],u*b0.w);
                    h[4]=fmaf(P[4],h[4],u*b1.x); h[5]=fmaf(P[5],h[5],u*b1.y);
                    h[6]=fmaf(P[6],h[6],u*b1.z); h[7]=fmaf(P[7],h[7],u*b1.w);
                    float4 c0 = *(const float4*)(cS + (s+1)*8);
                    float4 c1 = *(const float4*)(cS + (s+1)*8 + 4);
                    float a0 = h[0]*c0.x, a1 = h[1]*c0.y;
                    a0 = fmaf(h[2], c0.z, a0);  a1 = fmaf(h[3], c0.w, a1);
                    a0 = fmaf(h[4], c1.x, a0);  a1 = fmaf(h[5], c1.y, a1);
                    a0 = fmaf(h[6], c1.z, a0);  a1 = fmaf(h[7], c1.w, a1);
                    g_y[ybase + (s+1)*96] = a0 + a1;
                }
            }
            #pragma unroll
            for (int i = 0; i < 4; i++) buf[i] = nxt[i];
        }
    } else {
        const float2* eu2 = g_eu + base2;
        for (int s = 0; s < CS; s++){
            float2 eu = eu2[s];
            float delta = -__logf(fmaxf(eu.x, 1e-37f));
            float acc = 0.f;
            #pragma unroll
            for (int n = 0; n < 8; n++){
                float dA = __expf(delta*aN[n]);
                h[n] = fmaf(dA, h[n], eu.y*bS[s*8 + n]);
                acc  = fmaf(h[n], cS[s*8 + n], acc);
            }
            g_y[ybase + s*96] = acc;
        }
    }
}

// ---------------- K7: merge 4 directions + Ds*x + LN + gate + out-proj ----------------
// grid 256 (= B * 64 rows), block 192. Writes planar (b,c,p).
__global__ void k_out(const float* __restrict__ Ds, const float* __restrict__ lng,
                      const float* __restrict__ lnb, const float* __restrict__ ow,
                      float* __restrict__ dst){
    __shared__ __align__(16) float yoT[96*68];   // [d][m]
    __shared__ float meanS[64], rstdS[64];
    int t  = threadIdx.x;
    int b  = blockIdx.x >> 6;
    int p0 = (blockIdx.x & 63) << 6;
    for (int i = t; i < 6144; i += 192){
        int d = i % 96, m = i / 96;
        int p  = p0 + m;
        int pt = ((p & 63) << 6) | (p >> 6);
        float ds = __ldg(Ds + d) + __ldg(Ds + 96 + d) + __ldg(Ds + 192 + d) + __ldg(Ds + 288 + d);
        float v = g_y[((b*4 + 0)*LL + p)*96 + d]
                + g_y[((b*4 + 1)*LL + pt)*96 + d]
                + g_y[((b*4 + 2)*LL + (4095 - p))*96 + d]
                + g_y[((b*4 + 3)*LL + (4095 - pt))*96 + d]
                + ds * g_xc[(b*LL + p)*96 + d];
        yoT[d*68 + m] = v;
    }
    __syncthreads();
    if (t < 64){
        float s = 0.f, s2 = 0.f;
        for (int d = 0; d < 96; d++){ float v = yoT[d*68 + t]; s += v; s2 = fmaf(v, v, s2); }
        float mean = s * (1.f/96.f);
        float var  = s2 * (1.f/96.f) - mean*mean;
        meanS[t] = mean;
        rstdS[t] = rsqrtf(var + 1e-5f);
    }
    __syncthreads();
    for (int i = t; i < 6144; i += 192){
        int d = i % 96, m = i / 96;
        float v = (yoT[d*68 + m] - meanS[m]) * rstdS[m] * __ldg(lng + d) + __ldg(lnb + d);
        v *= g_z[(b*LL + p0 + m)*96 + d];
        yoT[d*68 + m] = v;
    }
    __syncthreads();
    {
        int c = t % 96, half = t / 96;
        int m0 = half*32;
        float acc[32];
        #pragma unroll
        for (int m = 0; m < 32; m++) acc[m] = 0.f;
        const float* wrow = ow + c*96;
        for (int d = 0; d < 96; d++){
            float wv = __ldg(wrow + d);
            const float4* yr = (const float4*)(yoT + d*68 + m0);
            #pragma unroll
            for (int m4 = 0; m4 < 8; m4++){
                float4 yv = yr[m4];
                acc[4*m4+0] = fmaf(wv, yv.x, acc[4*m4+0]);
                acc[4*m4+1] = fmaf(wv, yv.y, acc[4*m4+1]);
                acc[4*m4+2] = fmaf(wv, yv.z, acc[4*m4+2]);
                acc[4*m4+3] = fmaf(wv, yv.w, acc[4*m4+3]);
            }
        }
        float* orow = dst + (b*96 + c)*LL + p0 + m0;
        #pragma unroll
        for (int m = 0; m < 32; m++) orow[m] = acc[m];
    }
}

// ---------------- launcher ----------------
extern "C" void kernel_launch(void* const* d_in, const int* in_sizes, int n_in,
                              void* d_out, int out_size){
    (void)in_sizes; (void)n_in; (void)out_size;
    const float* input = (const float*)d_in[0];
    void* midp = nullptr;
    cudaGetSymbolAddress(&midp, g_mid);
    for (int blk = 0; blk < 2; blk++){
        const float* W[11];
        for (int i = 0; i < 11; i++) W[i] = (const float*)d_in[1 + blk*11 + i];
        const float* src = (blk == 0) ? input : (const float*)midp;
        float* dst = (blk == 0) ? (float*)midp : (float*)d_out;
        k_inproj<<<256, 192>>>(src, W[0]);
        k_conv  <<<6144, 256>>>(W[1], W[2]);
        k_xproj <<<2048, 256>>>(W[3], W[4], W[5]);
        k_scan1 <<<dim3(NCH, 16), 96>>>(W[6]);
        k_mid   <<<12, 128>>>();
        k_scan2 <<<dim3(NCH, 16), 96>>>(W[6]);
        k_out   <<<256, 192>>>(W[7], W[8], W[9], W[10], dst);
    }
}

// round 8
// speedup vs baseline: 1.0027x; 1.0027x over previous
#include <cuda_runtime.h>

#define BATCH 4
#define DD 96
#define NS 8
#define KD 4
#define LL 4096
#define CS 64     // chunk size (steps)
#define NCH 64    // number of chunks = LL/CS
#define NGRP 8    // CS/8

// ---------------- scratch (device globals; no allocation allowed) ----------------
__device__ float  g_xa [BATCH*LL*DD];
__device__ float  g_z  [BATCH*LL*DD];          // silu(z)
__device__ float  g_xc [BATCH*LL*DD];          // conv+silu output
__device__ float2 g_eu [BATCH*KD*LL*DD];       // {e1,u} ; layout [(bk*NCH+ch)*96+d]*CS + s
__device__ float  g_bB [BATCH*KD*LL*8];        // B
__device__ float  g_bC [BATCH*KD*LL*8];        // C
__device__ float  g_y  [BATCH*KD*LL*DD];       // scan output per direction
__device__ float  g_hp [BATCH*KD*NCH*16*DD];   // per-chunk {h_end(8),P(8)} comp-major [..][comp][d]
__device__ float  g_hin[BATCH*KD*NCH*8*DD];    // per-chunk incoming state comp-major
__device__ float  g_mid[BATCH*DD*LL];          // inter-block activation, planar (b,c,p)

// ---------------- K1: in-projection GEMM (planar (b,c,p) -> xa, silu(z)) --------
// grid 256 (= B * L/64), block 192. Each CTA: 64 positions, 192 output channels.
__global__ void k_inproj(const float* __restrict__ src, const float* __restrict__ in_w){
    __shared__ __align__(16) float sm[64*97];   // union: X[96][64] then OUT[64][97]
    int b  = blockIdx.x >> 6;
    int p0 = (blockIdx.x & 63) << 6;
    int t  = threadIdx.x;
    for (int i = t; i < 96*64; i += 192){
        int c = i >> 6, m = i & 63;
        sm[i] = src[((b*96 + c) << 12) + p0 + m];
    }
    __syncthreads();
    float acc[64];
    #pragma unroll
    for (int m = 0; m < 64; m++) acc[m] = 0.f;
    const float* wrow = in_w + t*96;
    for (int c = 0; c < 96; c++){
        float wv = __ldg(wrow + c);
        const float4* xr = (const float4*)(sm + (c<<6));
        #pragma unroll
        for (int m4 = 0; m4 < 16; m4++){
            float4 xv = xr[m4];
            acc[4*m4+0] = fmaf(wv, xv.x, acc[4*m4+0]);
            acc[4*m4+1] = fmaf(wv, xv.y, acc[4*m4+1]);
            acc[4*m4+2] = fmaf(wv, xv.z, acc[4*m4+2]);
            acc[4*m4+3] = fmaf(wv, xv.w, acc[4*m4+3]);
        }
    }
    __syncthreads();
    if (t < 96){
        #pragma unroll
        for (int m = 0; m < 64; m++) sm[m*97 + t] = acc[m];
    }
    __syncthreads();
    for (int i = t; i < 64*96; i += 192){
        int m = i/96, d = i - m*96;
        g_xa[(b*LL + p0 + m)*96 + d] = sm[m*97 + d];
    }
    __syncthreads();
    if (t >= 96){
        #pragma unroll
        for (int m = 0; m < 64; m++) sm[m*97 + (t-96)] = acc[m];
    }
    __syncthreads();
    for (int i = t; i < 64*96; i += 192){
        int m = i/96, d = i - m*96;
        float v = sm[m*97 + d];
        g_z[(b*LL + p0 + m)*96 + d] = v * __fdividef(1.f, 1.f + __expf(-v));
    }
}

// ---------------- K2: depthwise 3x3 conv + bias + silu ----------------
// grid 6144, block 256 : one thread per (b,p,d)
__global__ void k_conv(const float* __restrict__ cw, const float* __restrict__ cb){
    int idx = blockIdx.x*256 + threadIdx.x;
    int d  = idx % 96;
    int pp = idx / 96;
    int p  = pp & 4095, b = pp >> 12;
    int h  = p >> 6,    w = p & 63;
    const float* wt = cw + d*9;
    float a = 0.f;
    #pragma unroll
    for (int i = 0; i < 3; i++){
        int hh = h + i - 1;
        if ((unsigned)hh < 64u){
            #pragma unroll
            for (int j = 0; j < 3; j++){
                int ww = w + j - 1;
                if ((unsigned)ww < 64u)
                    a = fmaf(__ldg(wt + i*3 + j), g_xa[(b*LL + (hh<<6) + ww)*96 + d], a);
            }
        }
    }
    a += __ldg(cb + d);
    g_xc[idx] = a * __fdividef(1.f, 1.f + __expf(-a));
}

// direction index map: scan step l of direction k reads spatial position perm(k,l)
__device__ __forceinline__ int perm_idx(int k, int l){
    if (k == 0) return l;
    if (k == 1) return ((l & 63) << 6) | (l >> 6);
    if (k == 2) return 4095 - l;
    int m = 4095 - l; return ((m & 63) << 6) | (m >> 6);
}

// ---------------- K3: x-projection + dt + softplus precompute ----------------
// grid 2048 (= B*K * L/32), block 256
__global__ void __launch_bounds__(256) k_xproj(const float* __restrict__ xpw,
                        const float* __restrict__ dtw, const float* __restrict__ dtb){
    __shared__ __align__(16) float xvS[32*100];
    __shared__ float xdbl[32*25];
    __shared__ __align__(16) float xpS[22*96];
    __shared__ float dtwS[96*6];
    __shared__ float dtbS[96];
    int t   = threadIdx.x;
    int g   = blockIdx.x;
    int seg = g & 127, bk = g >> 7;
    int b   = bk >> 2,  k = bk & 3;
    int l0  = seg << 5;
    for (int i = t; i < 22*96; i += 256) xpS[i]  = xpw[k*22*96 + i];
    for (int i = t; i < 96*6;  i += 256) dtwS[i] = dtw[k*96*6 + i];
    if (t < 96) dtbS[t] = dtb[k*96 + t];
    for (int i = t; i < 32*96; i += 256){
        int m = i/96, d = i - m*96;
        int p = perm_idx(k, l0 + m);
        xvS[m*100 + d] = g_xc[(b*LL + p)*96 + d];
    }
    __syncthreads();
    for (int j = t; j < 704; j += 256){
        int m = j/22, c = j - m*22;
        const float4* a4 = (const float4*)(xpS + c*96);
        const float4* x4 = (const float4*)(xvS + m*100);
        float acc = 0.f;
        #pragma unroll
        for (int q = 0; q < 24; q++){
            float4 av = a4[q], xv = x4[q];
            acc += av.x*xv.x + av.y*xv.y + av.z*xv.z + av.w*xv.w;
        }
        xdbl[m*25 + c] = acc;
    }
    __syncthreads();
    // chunk-major eu write: chunk = seg>>1, base step = (seg&1)*32
    int chunk = seg >> 1, s0 = (seg & 1) << 5;
    for (int j = t; j < 32*96; j += 256){
        int m = j & 31, d = j >> 5;        // m fastest -> contiguous stores
        float s = dtbS[d];
        #pragma unroll
        for (int r = 0; r < 6; r++) s = fmaf(dtwS[d*6 + r], xdbl[m*25 + r], s);
        float et    = __expf(fminf(s, 60.f));
        float delta = (s > 15.f) ? s : __logf(1.f + et);   // softplus
        float e1    = __fdividef(1.f, 1.f + et);           // exp(-softplus(s))
        g_eu[((bk*NCH + chunk)*96 + d)*CS + s0 + m] = make_float2(e1, delta * xvS[m*100 + d]);
    }
    {
        int m = t >> 3, i = t & 7;   // 256 threads cover 32*8 exactly
        g_bB[(bk*LL + l0 + m)*8 + i] = xdbl[m*25 + 6 + i];
        g_bC[(bk*LL + l0 + m)*8 + i] = xdbl[m*25 + 14 + i];
    }
}

// log-depth powers e1^1..e1^8
#define POWER_TREE(e1, P)                                     \
    { P[0]=e1; P[1]=e1*e1; P[3]=P[1]*P[1]; P[2]=P[1]*e1;      \
      P[4]=P[3]*e1; P[5]=P[3]*P[1]; P[6]=P[3]*P[2]; P[7]=P[3]*P[3]; }

// ---------------- K4: scan pass 1 (per-chunk h_end and A-product) ----------------
// grid (NCH, 16), block 96
__global__ void __launch_bounds__(96) k_scan1(const float* __restrict__ alogs){
    __shared__ __align__(16) float bS[CS*8];
    int chunk = blockIdx.x, bk = blockIdx.y;
    int k = bk & 3;
    int d = threadIdx.x;
    int l0 = chunk*CS;
    for (int i = d; i < CS*8; i += 96) bS[i] = g_bB[(bk*LL + l0)*8 + i];
    float aN[8]; bool fast = true;
    const float* arow = alogs + (k*96 + d)*8;
    #pragma unroll
    for (int n = 0; n < 8; n++){
        float a = -__expf(arow[n]); aN[n] = a;
        fast = fast && (fabsf(a + (float)(n+1)) < 1e-3f*(float)(n+1));
    }
    __syncthreads();
    float h[8];
    #pragma unroll
    for (int n = 0; n < 8; n++) h[n] = 0.f;
    int base2 = ((bk*NCH + chunk)*96 + d)*CS;
    int ob = (bk*NCH + chunk)*16*96 + d;    // comp-major: +comp*96
    if (fast){
        const float4* eu4 = (const float4*)(g_eu + base2);  // 2 steps per float4
        float4 buf[4];
        #pragma unroll
        for (int i = 0; i < 4; i++) buf[i] = eu4[i];
        float q = 1.f;
        for (int grp = 0; grp < NGRP; grp++){
            float4 nxt[4];
            if (grp + 1 < NGRP){
                #pragma unroll
                for (int i = 0; i < 4; i++) nxt[i] = eu4[(grp+1)*4 + i];
            }
            #pragma unroll
            for (int i = 0; i < 4; i++){
                int s = grp*8 + i*2;
                {   float e1 = buf[i].x, u = buf[i].y;
                    float P[8]; POWER_TREE(e1, P);
                    q *= e1;
                    float4 b0 = *(const float4*)(bS + s*8);
                    float4 b1 = *(const float4*)(bS + s*8 + 4);
                    h[0]=fmaf(P[0],h[0],u*b0.x); h[1]=fmaf(P[1],h[1],u*b0.y);
                    h[2]=fmaf(P[2],h[2],u*b0.z); h[3]=fmaf(P[3],h[3],u*b0.w);
                    h[4]=fmaf(P[4],h[4],u*b1.x); h[5]=fmaf(P[5],h[5],u*b1.y);
                    h[6]=fmaf(P[6],h[6],u*b1.z); h[7]=fmaf(P[7],h[7],u*b1.w);
                }
                {   float e1 = buf[i].z, u = buf[i].w;
                    float P[8]; POWER_TREE(e1, P);
                    q *= e1;
                    float4 b0 = *(const float4*)(bS + (s+1)*8);
                    float4 b1 = *(const float4*)(bS + (s+1)*8 + 4);
                    h[0]=fmaf(P[0],h[0],u*b0.x); h[1]=fmaf(P[1],h[1],u*b0.y);
                    h[2]=fmaf(P[2],h[2],u*b0.z); h[3]=fmaf(P[3],h[3],u*b0.w);
                    h[4]=fmaf(P[4],h[4],u*b1.x); h[5]=fmaf(P[5],h[5],u*b1.y);
                    h[6]=fmaf(P[6],h[6],u*b1.z); h[7]=fmaf(P[7],h[7],u*b1.w);
                }
            }
            #pragma unroll
            for (int i = 0; i < 4; i++) buf[i] = nxt[i];
        }
        float P[8]; POWER_TREE(q, P);
        #pragma unroll
        for (int n = 0; n < 8; n++){ g_hp[ob + n*96] = h[n]; g_hp[ob + (8+n)*96] = P[n]; }
    } else {
        const float2* eu2 = g_eu + base2;
        float P[8];
        #pragma unroll
        for (int n = 0; n < 8; n++) P[n] = 1.f;
        for (int s = 0; s < CS; s++){
            float2 eu = eu2[s];
            float delta = -__logf(fmaxf(eu.x, 1e-37f));
            #pragma unroll
            for (int n = 0; n < 8; n++){
                float dA = __expf(delta*aN[n]);
                h[n] = fmaf(dA, h[n], eu.y*bS[s*8 + n]);
                P[n] *= dA;
            }
        }
        #pragma unroll
        for (int n = 0; n < 8; n++){ g_hp[ob + n*96] = h[n]; g_hp[ob + (8+n)*96] = P[n]; }
    }
}

// ---------------- K5: chunk-boundary scan (tiny, coalesced + prefetched) ----------------
__global__ void k_mid(){
    int t = blockIdx.x*128 + threadIdx.x;
    if (t >= 16*96) return;
    int bk = t/96, d = t - bk*96;
    float h[8];
    #pragma unroll
    for (int n = 0; n < 8; n++) h[n] = 0.f;
    float cur[16];
    {
        int hb = (bk*NCH)*16*96 + d;
        #pragma unroll
        for (int i = 0; i < 16; i++) cur[i] = g_hp[hb + i*96];
    }
    for (int c = 0; c < NCH; c++){
        float nxt[16];
        if (c + 1 < NCH){
            int hb = (bk*NCH + c + 1)*16*96 + d;
            #pragma unroll
            for (int i = 0; i < 16; i++) nxt[i] = g_hp[hb + i*96];
        }
        int ib = (bk*NCH + c)*8*96 + d;
        #pragma unroll
        for (int n = 0; n < 8; n++) g_hin[ib + n*96] = h[n];
        #pragma unroll
        for (int n = 0; n < 8; n++) h[n] = fmaf(cur[8+n], h[n], cur[n]);
        #pragma unroll
        for (int i = 0; i < 16; i++) cur[i] = nxt[i];
    }
}

// ---------------- K6: scan pass 2 (seeded recompute, emit y) ----------------
__global__ void __launch_bounds__(96) k_scan2(const float* __restrict__ alogs){
    __shared__ __align__(16) float bS[CS*8];
    __shared__ __align__(16) float cS[CS*8];
    int chunk = blockIdx.x, bk = blockIdx.y;
    int k = bk & 3;
    int d = threadIdx.x;
    int l0 = chunk*CS;
    for (int i = d; i < CS*8; i += 96){
        bS[i] = g_bB[(bk*LL + l0)*8 + i];
        cS[i] = g_bC[(bk*LL + l0)*8 + i];
    }
    float aN[8]; bool fast = true;
    const float* arow = alogs + (k*96 + d)*8;
    #pragma unroll
    for (int n = 0; n < 8; n++){
        float a = -__expf(arow[n]); aN[n] = a;
        fast = fast && (fabsf(a + (float)(n+1)) < 1e-3f*(float)(n+1));
    }
    float h[8];
    {
        int ib = (bk*NCH + chunk)*8*96 + d;
        #pragma unroll
        for (int n = 0; n < 8; n++) h[n] = g_hin[ib + n*96];
    }
    __syncthreads();
    int base2 = ((bk*NCH + chunk)*96 + d)*CS;
    int ybase = (bk*LL + l0)*96 + d;
    if (fast){
        const float4* eu4 = (const float4*)(g_eu + base2);
        float4 buf[4];
        #pragma unroll
        for (int i = 0; i < 4; i++) buf[i] = eu4[i];
        for (int grp = 0; grp < NGRP; grp++){
            float4 nxt[4];
            if (grp + 1 < NGRP){
                #pragma unroll
                for (int i = 0; i < 4; i++) nxt[i] = eu4[(grp+1)*4 + i];
            }
            #pragma unroll
            for (int i = 0; i < 4; i++){
                int s = grp*8 + i*2;
                {   float e1 = buf[i].x, u = buf[i].y;
                    float P[8]; POWER_TREE(e1, P);
                    float4 b0 = *(const float4*)(bS + s*8);
                    float4 b1 = *(const float4*)(bS + s*8 + 4);
                    h[0]=fmaf(P[0],h[0],u*b0.x); h[1]=fmaf(P[1],h[1],u*b0.y);
                    h[2]=fmaf(P[2],h[2],u*b0.z); h[3]=fmaf(P[3],h[3],u*b0.w);
                    h[4]=fmaf(P[4],h[4],u*b1.x); h[5]=fmaf(P[5],h[5],u*b1.y);
                    h[6]=fmaf(P[6],h[6],u*b1.z); h[7]=fmaf(P[7],h[7],u*b1.w);
                    float4 c0 = *(const float4*)(cS + s*8);
                    float4 c1 = *(const float4*)(cS + s*8 + 4);
                    float a0 = h[0]*c0.x, a1 = h[1]*c0.y;
                    a0 = fmaf(h[2], c0.z, a0);  a1 = fmaf(h[3], c0.w, a1);
                    a0 = fmaf(h[4], c1.x, a0);  a1 = fmaf(h[5], c1.y, a1);
                    a0 = fmaf(h[6], c1.z, a0);  a1 = fmaf(h[7], c1.w, a1);
                    g_y[ybase + s*96] = a0 + a1;
                }
                {   float e1 = buf[i].z, u = buf[i].w;
                    float P[8]; POWER_TREE(e1, P);
                    float4 b0 = *(const float4*)(bS + (s+1)*8);
                    float4 b1 = *(const float4*)(bS + (s+1)*8 + 4);
                    h[0]=fmaf(P[0],h[0],u*b0.x); h[1]=fmaf(P[1],h[1],u*b0.y);
                    h[2]=fmaf(P[2],h[2],u*b0.z); h[3]=fmaf(P[3],h[3],u*b0.w);
                    h[4]=fmaf(P[4],h[4],u*b1.x); h[5]=fmaf(P[5],h[5],u*b1.y);
                    h[6]=fmaf(P[6],h[6],u*b1.z); h[7]=fmaf(P[7],h[7],u*b1.w);
                    float4 c0 = *(const float4*)(cS + (s+1)*8);
                    float4 c1 = *(const float4*)(cS + (s+1)*8 + 4);
                    float a0 = h[0]*c0.x, a1 = h[1]*c0.y;
                    a0 = fmaf(h[2], c0.z, a0);  a1 = fmaf(h[3], c0.w, a1);
                    a0 = fmaf(h[4], c1.x, a0);  a1 = fmaf(h[5], c1.y, a1);
                    a0 = fmaf(h[6], c1.z, a0);  a1 = fmaf(h[7], c1.w, a1);
                    g_y[ybase + (s+1)*96] = a0 + a1;
                }
            }
            #pragma unroll
            for (int i = 0; i < 4; i++) buf[i] = nxt[i];
        }
    } else {
        const float2* eu2 = g_eu + base2;
        for (int s = 0; s < CS; s++){
            float2 eu = eu2[s];
            float delta = -__logf(fmaxf(eu.x, 1e-37f));
            float acc = 0.f;
            #pragma unroll
            for (int n = 0; n < 8; n++){
                float dA = __expf(delta*aN[n]);
                h[n] = fmaf(dA, h[n], eu.y*bS[s*8 + n]);
                acc  = fmaf(h[n], cS[s*8 + n], acc);
            }
            g_y[ybase + s*96] = acc;
        }
    }
}

// ---------------- K7: merge 4 directions + Ds*x + LN + gate + out-proj ----------------
// grid 256 (= B * 64 rows), block 192. Writes planar (b,c,p).
__global__ void k_out(const float* __restrict__ Ds, const float* __restrict__ lng,
                      const float* __restrict__ lnb, const float* __restrict__ ow,
                      float* __restrict__ dst){
    __shared__ __align__(16) float yoT[96*68];   // [d][m]
    __shared__ float meanS[64], rstdS[64];
    int t  = threadIdx.x;
    int b  = blockIdx.x >> 6;
    int p0 = (blockIdx.x & 63) << 6;
    for (int i = t; i < 6144; i += 192){
        int d = i % 96, m = i / 96;
        int p  = p0 + m;
        int pt = ((p & 63) << 6) | (p >> 6);
        float ds = __ldg(Ds + d) + __ldg(Ds + 96 + d) + __ldg(Ds + 192 + d) + __ldg(Ds + 288 + d);
        float v = g_y[((b*4 + 0)*LL + p)*96 + d]
                + g_y[((b*4 + 1)*LL + pt)*96 + d]
                + g_y[((b*4 + 2)*LL + (4095 - p))*96 + d]
                + g_y[((b*4 + 3)*LL + (4095 - pt))*96 + d]
                + ds * g_xc[(b*LL + p)*96 + d];
        yoT[d*68 + m] = v;
    }
    __syncthreads();
    if (t < 64){
        float s = 0.f, s2 = 0.f;
        for (int d = 0; d < 96; d++){ float v = yoT[d*68 + t]; s += v; s2 = fmaf(v, v, s2); }
        float mean = s * (1.f/96.f);
        float var  = s2 * (1.f/96.f) - mean*mean;
        meanS[t] = mean;
        rstdS[t] = rsqrtf(var + 1e-5f);
    }
    __syncthreads();
    for (int i = t; i < 6144; i += 192){
        int d = i % 96, m = i / 96;
        float v = (yoT[d*68 + m] - meanS[m]) * rstdS[m] * __ldg(lng + d) + __ldg(lnb + d);
        v *= g_z[(b*LL + p0 + m)*96 + d];
        yoT[d*68 + m] = v;
    }
    __syncthreads();
    {
        int c = t % 96, half = t / 96;
        int m0 = half*32;
        float acc[32];
        #pragma unroll
        for (int m = 0; m < 32; m++) acc[m] = 0.f;
        const float* wrow = ow + c*96;
        for (int d = 0; d < 96; d++){
            float wv = __ldg(wrow + d);
            const float4* yr = (const float4*)(yoT + d*68 + m0);
            #pragma unroll
            for (int m4 = 0; m4 < 8; m4++){
                float4 yv = yr[m4];
                acc[4*m4+0] = fmaf(wv, yv.x, acc[4*m4+0]);
                acc[4*m4+1] = fmaf(wv, yv.y, acc[4*m4+1]);
                acc[4*m4+2] = fmaf(wv, yv.z, acc[4*m4+2]);
                acc[4*m4+3] = fmaf(wv, yv.w, acc[4*m4+3]);
            }
        }
        float* orow = dst + (b*96 + c)*LL + p0 + m0;
        #pragma unroll
        for (int m = 0; m < 32; m++) orow[m] = acc[m];
    }
}

// ---------------- launcher ----------------
extern "C" void kernel_launch(void* const* d_in, const int* in_sizes, int n_in,
                              void* d_out, int out_size){
    (void)in_sizes; (void)n_in; (void)out_size;
    const float* input = (const float*)d_in[0];
    void* midp = nullptr;
    cudaGetSymbolAddress(&midp, g_mid);
    for (int blk = 0; blk < 2; blk++){
        const float* W[11];
        for (int i = 0; i < 11; i++) W[i] = (const float*)d_in[1 + blk*11 + i];
        const float* src = (blk == 0) ? input : (const float*)midp;
        float* dst = (blk == 0) ? (float*)midp : (float*)d_out;
        k_inproj<<<256, 192>>>(src, W[0]);
        k_conv  <<<6144, 256>>>(W[1], W[2]);
        k_xproj <<<2048, 256>>>(W[3], W[4], W[5]);
        k_scan1 <<<dim3(NCH, 16), 96>>>(W[6]);
        k_mid   <<<12, 128>>>();
        k_scan2 <<<dim3(NCH, 16), 96>>>(W[6]);
        k_out   <<<256, 192>>>(W[7], W[8], W[9], W[10], dst);
    }
}

// round 9
// speedup vs baseline: 1.5070x; 1.5029x over previous
#include <cuda_runtime.h>

#define BATCH 4
#define DD 96
#define NS 8
#define KD 4
#define LL 4096
#define CS 64     // chunk size (steps)
#define NCH 64    // number of chunks = LL/CS
#define NGRP 8    // CS/8

// ---------------- scratch (device globals; no allocation allowed) ----------------
__device__ float  g_xa [BATCH*LL*DD];
__device__ float  g_z  [BATCH*LL*DD];          // silu(z)
__device__ float  g_xc [BATCH*LL*DD];          // conv+silu output
__device__ float2 g_eu [BATCH*KD*LL*DD];       // {e1,u} ; layout [(bk*NCH+ch)*96+d]*CS + s
__device__ float  g_bB [BATCH*KD*LL*8];        // B
__device__ float  g_bC [BATCH*KD*LL*8];        // C
__device__ float  g_y  [BATCH*KD*LL*DD];       // scan output per direction
__device__ float  g_hp [BATCH*KD*NCH*16*DD];   // per-chunk {h_end(8),P(8)} comp-major [..][comp][d]
__device__ float  g_hin[BATCH*KD*NCH*8*DD];    // per-chunk incoming state comp-major
__device__ float  g_mid[BATCH*DD*LL];          // inter-block activation, planar (b,c,p)

// ---------------- K1: in-projection GEMM (planar (b,c,p) -> xa, silu(z)) --------
// grid 256 (= B * L/64), block 192. Each CTA: 64 positions, 192 output channels.
__global__ void k_inproj(const float* __restrict__ src, const float* __restrict__ in_w){
    __shared__ __align__(16) float sm[64*97];   // union: X[96][64] then OUT[64][97]
    int b  = blockIdx.x >> 6;
    int p0 = (blockIdx.x & 63) << 6;
    int t  = threadIdx.x;
    for (int i = t; i < 96*64; i += 192){
        int c = i >> 6, m = i & 63;
        sm[i] = src[((b*96 + c) << 12) + p0 + m];
    }
    __syncthreads();
    float acc[64];
    #pragma unroll
    for (int m = 0; m < 64; m++) acc[m] = 0.f;
    const float* wrow = in_w + t*96;
    for (int c = 0; c < 96; c++){
        float wv = __ldg(wrow + c);
        const float4* xr = (const float4*)(sm + (c<<6));
        #pragma unroll
        for (int m4 = 0; m4 < 16; m4++){
            float4 xv = xr[m4];
            acc[4*m4+0] = fmaf(wv, xv.x, acc[4*m4+0]);
            acc[4*m4+1] = fmaf(wv, xv.y, acc[4*m4+1]);
            acc[4*m4+2] = fmaf(wv, xv.z, acc[4*m4+2]);
            acc[4*m4+3] = fmaf(wv, xv.w, acc[4*m4+3]);
        }
    }
    __syncthreads();
    if (t < 96){
        #pragma unroll
        for (int m = 0; m < 64; m++) sm[m*97 + t] = acc[m];
    }
    __syncthreads();
    for (int i = t; i < 64*96; i += 192){
        int m = i/96, d = i - m*96;
        g_xa[(b*LL + p0 + m)*96 + d] = sm[m*97 + d];
    }
    __syncthreads();
    if (t >= 96){
        #pragma unroll
        for (int m = 0; m < 64; m++) sm[m*97 + (t-96)] = acc[m];
    }
    __syncthreads();
    for (int i = t; i < 64*96; i += 192){
        int m = i/96, d = i - m*96;
        float v = sm[m*97 + d];
        g_z[(b*LL + p0 + m)*96 + d] = v * __fdividef(1.f, 1.f + __expf(-v));
    }
}

// ---------------- K2: depthwise 3x3 conv + bias + silu ----------------
// grid 6144, block 256 : one thread per (b,p,d)
__global__ void k_conv(const float* __restrict__ cw, const float* __restrict__ cb){
    int idx = blockIdx.x*256 + threadIdx.x;
    int d  = idx % 96;
    int pp = idx / 96;
    int p  = pp & 4095, b = pp >> 12;
    int h  = p >> 6,    w = p & 63;
    const float* wt = cw + d*9;
    float a = 0.f;
    #pragma unroll
    for (int i = 0; i < 3; i++){
        int hh = h + i - 1;
        if ((unsigned)hh < 64u){
            #pragma unroll
            for (int j = 0; j < 3; j++){
                int ww = w + j - 1;
                if ((unsigned)ww < 64u)
                    a = fmaf(__ldg(wt + i*3 + j), g_xa[(b*LL + (hh<<6) + ww)*96 + d], a);
            }
        }
    }
    a += __ldg(cb + d);
    g_xc[idx] = a * __fdividef(1.f, 1.f + __expf(-a));
}

// direction index map: scan step l of direction k reads spatial position perm(k,l)
__device__ __forceinline__ int perm_idx(int k, int l){
    if (k == 0) return l;
    if (k == 1) return ((l & 63) << 6) | (l >> 6);
    if (k == 2) return 4095 - l;
    int m = 4095 - l; return ((m & 63) << 6) | (m >> 6);
}

// ---------------- K3: x-projection + dt + softplus precompute ----------------
// grid 2048 (= B*K * L/32), block 256
// xvT is [d][m] with pad 33 -> conflict-free LDS everywhere; xp reads are warp-broadcast.
__global__ void __launch_bounds__(256) k_xproj(const float* __restrict__ xpw,
                        const float* __restrict__ dtw, const float* __restrict__ dtb){
    __shared__ float xvT[96*33];       // [d][m]
    __shared__ float xdbl[32*25];
    __shared__ float xpS[22*96];
    __shared__ float dtwS[96*6];
    __shared__ float dtbS[96];
    int t   = threadIdx.x;
    int g   = blockIdx.x;
    int seg = g & 127, bk = g >> 7;
    int b   = bk >> 2,  k = bk & 3;
    int l0  = seg << 5;
    for (int i = t; i < 22*96; i += 256) xpS[i]  = xpw[k*22*96 + i];
    for (int i = t; i < 96*6;  i += 256) dtwS[i] = dtw[k*96*6 + i];
    if (t < 96) dtbS[t] = dtb[k*96 + t];
    for (int i = t; i < 32*96; i += 256){
        int m = i/96, d = i - m*96;
        int p = perm_idx(k, l0 + m);
        xvT[d*33 + m] = g_xc[(b*LL + p)*96 + d];
    }
    __syncthreads();
    // GEMM: 22 channels x 32 positions. lane = m (conflict-free xvT), warp-uniform c (broadcast xpS).
    {
        int m  = t & 31;
        int c0 = t >> 5;            // 0..7
        int c1 = c0 + 8;            // 8..15
        int c2 = c0 + 16;           // 16..23 (valid if < 22)
        float a0 = 0.f, a1 = 0.f, a2 = 0.f;
        const float* xp0 = xpS + c0*96;
        const float* xp1 = xpS + c1*96;
        const float* xp2 = xpS + (c2 < 22 ? c2 : 0)*96;
        #pragma unroll 4
        for (int d = 0; d < 96; d++){
            float xv = xvT[d*33 + m];
            a0 = fmaf(xp0[d], xv, a0);
            a1 = fmaf(xp1[d], xv, a1);
            a2 = fmaf(xp2[d], xv, a2);
        }
        xdbl[m*25 + c0] = a0;
        xdbl[m*25 + c1] = a1;
        if (c2 < 22) xdbl[m*25 + c2] = a2;
    }
    __syncthreads();
    // chunk-major eu write: chunk = seg>>1, base step = (seg&1)*32
    int chunk = seg >> 1, s0 = (seg & 1) << 5;
    for (int j = t; j < 32*96; j += 256){
        int m = j & 31, d = j >> 5;        // m fastest -> contiguous stores
        float s = dtbS[d];
        #pragma unroll
        for (int r = 0; r < 6; r++) s = fmaf(dtwS[d*6 + r], xdbl[m*25 + r], s);
        float et    = __expf(fminf(s, 60.f));
        float delta = (s > 15.f) ? s : __logf(1.f + et);   // softplus
        float e1    = __fdividef(1.f, 1.f + et);           // exp(-softplus(s))
        g_eu[((bk*NCH + chunk)*96 + d)*CS + s0 + m] = make_float2(e1, delta * xvT[d*33 + m]);
    }
    {
        int m = t >> 3, i = t & 7;   // 256 threads cover 32*8 exactly
        g_bB[(bk*LL + l0 + m)*8 + i] = xdbl[m*25 + 6 + i];
        g_bC[(bk*LL + l0 + m)*8 + i] = xdbl[m*25 + 14 + i];
    }
}

// log-depth powers e1^1..e1^8
#define POWER_TREE(e1, P)                                     \
    { P[0]=e1; P[1]=e1*e1; P[3]=P[1]*P[1]; P[2]=P[1]*e1;      \
      P[4]=P[3]*e1; P[5]=P[3]*P[1]; P[6]=P[3]*P[2]; P[7]=P[3]*P[3]; }

// ---------------- K4: scan pass 1 (per-chunk h_end and A-product) ----------------
// grid (NCH, 16), block 96
__global__ void __launch_bounds__(96) k_scan1(const float* __restrict__ alogs){
    __shared__ __align__(16) float bS[CS*8];
    int chunk = blockIdx.x, bk = blockIdx.y;
    int k = bk & 3;
    int d = threadIdx.x;
    int l0 = chunk*CS;
    for (int i = d; i < CS*8; i += 96) bS[i] = g_bB[(bk*LL + l0)*8 + i];
    float aN[8]; bool fast = true;
    const float* arow = alogs + (k*96 + d)*8;
    #pragma unroll
    for (int n = 0; n < 8; n++){
        float a = -__expf(arow[n]); aN[n] = a;
        fast = fast && (fabsf(a + (float)(n+1)) < 1e-3f*(float)(n+1));
    }
    __syncthreads();
    float h[8];
    #pragma unroll
    for (int n = 0; n < 8; n++) h[n] = 0.f;
    int base2 = ((bk*NCH + chunk)*96 + d)*CS;
    int ob = (bk*NCH + chunk)*16*96 + d;    // comp-major: +comp*96
    if (fast){
        const float4* eu4 = (const float4*)(g_eu + base2);  // 2 steps per float4
        float4 buf[4];
        #pragma unroll
        for (int i = 0; i < 4; i++) buf[i] = eu4[i];
        float q = 1.f;
        for (int grp = 0; grp < NGRP; grp++){
            float4 nxt[4];
            if (grp + 1 < NGRP){
                #pragma unroll
                for (int i = 0; i < 4; i++) nxt[i] = eu4[(grp+1)*4 + i];
            }
            #pragma unroll
            for (int i = 0; i < 4; i++){
                int s = grp*8 + i*2;
                {   float e1 = buf[i].x, u = buf[i].y;
                    float P[8]; POWER_TREE(e1, P);
                    q *= e1;
                    float4 b0 = *(const float4*)(bS + s*8);
                    float4 b1 = *(const float4*)(bS + s*8 + 4);
                    h[0]=fmaf(P[0],h[0],u*b0.x); h[1]=fmaf(P[1],h[1],u*b0.y);
                    h[2]=fmaf(P[2],h[2],u*b0.z); h[3]=fmaf(P[3],h[3],u*b0.w);
                    h[4]=fmaf(P[4],h[4],u*b1.x); h[5]=fmaf(P[5],h[5],u*b1.y);
                    h[6]=fmaf(P[6],h[6],u*b1.z); h[7]=fmaf(P[7],h[7],u*b1.w);
                }
                {   float e1 = buf[i].z, u = buf[i].w;
                    float P[8]; POWER_TREE(e1, P);
                    q *= e1;
                    float4 b0 = *(const float4*)(bS + (s+1)*8);
                    float4 b1 = *(const float4*)(bS + (s+1)*8 + 4);
                    h[0]=fmaf(P[0],h[0],u*b0.x); h[1]=fmaf(P[1],h[1],u*b0.y);
                    h[2]=fmaf(P[2],h[2],u*b0.z); h[3]=fmaf(P[3],h[3],u*b0.w);
                    h[4]=fmaf(P[4],h[4],u*b1.x); h[5]=fmaf(P[5],h[5],u*b1.y);
                    h[6]=fmaf(P[6],h[6],u*b1.z); h[7]=fmaf(P[7],h[7],u*b1.w);
                }
            }
            #pragma unroll
            for (int i = 0; i < 4; i++) buf[i] = nxt[i];
        }
        float P[8]; POWER_TREE(q, P);
        #pragma unroll
        for (int n = 0; n < 8; n++){ g_hp[ob + n*96] = h[n]; g_hp[ob + (8+n)*96] = P[n]; }
    } else {
        const float2* eu2 = g_eu + base2;
        float P[8];
        #pragma unroll
        for (int n = 0; n < 8; n++) P[n] = 1.f;
        for (int s = 0; s < CS; s++){
            float2 eu = eu2[s];
            float delta = -__logf(fmaxf(eu.x, 1e-37f));
            #pragma unroll
            for (int n = 0; n < 8; n++){
                float dA = __expf(delta*aN[n]);
                h[n] = fmaf(dA, h[n], eu.y*bS[s*8 + n]);
                P[n] *= dA;
            }
        }
        #pragma unroll
        for (int n = 0; n < 8; n++){ g_hp[ob + n*96] = h[n]; g_hp[ob + (8+n)*96] = P[n]; }
    }
}

// ---------------- K5: chunk-boundary scan (tiny, coalesced + prefetched) ----------------
__global__ void k_mid(){
    int t = blockIdx.x*128 + threadIdx.x;
    if (t >= 16*96) return;
    int bk = t/96, d = t - bk*96;
    float h[8];
    #pragma unroll
    for (int n = 0; n < 8; n++) h[n] = 0.f;
    float cur[16];
    {
        int hb = (bk*NCH)*16*96 + d;
        #pragma unroll
        for (int i = 0; i < 16; i++) cur[i] = g_hp[hb + i*96];
    }
    for (int c = 0; c < NCH; c++){
        float nxt[16];
        if (c + 1 < NCH){
            int hb = (bk*NCH + c + 1)*16*96 + d;
            #pragma unroll
            for (int i = 0; i < 16; i++) nxt[i] = g_hp[hb + i*96];
        }
        int ib = (bk*NCH + c)*8*96 + d;
        #pragma unroll
        for (int n = 0; n < 8; n++) g_hin[ib + n*96] = h[n];
        #pragma unroll
        for (int n = 0; n < 8; n++) h[n] = fmaf(cur[8+n], h[n], cur[n]);
        #pragma unroll
        for (int i = 0; i < 16; i++) cur[i] = nxt[i];
    }
}

// ---------------- K6: scan pass 2 (seeded recompute, emit y) ----------------
__global__ void __launch_bounds__(96) k_scan2(const float* __restrict__ alogs){
    __shared__ __align__(16) float bS[CS*8];
    __shared__ __align__(16) float cS[CS*8];
    int chunk = blockIdx.x, bk = blockIdx.y;
    int k = bk & 3;
    int d = threadIdx.x;
    int l0 = chunk*CS;
    for (int i = d; i < CS*8; i += 96){
        bS[i] = g_bB[(bk*LL + l0)*8 + i];
        cS[i] = g_bC[(bk*LL + l0)*8 + i];
    }
    float aN[8]; bool fast = true;
    const float* arow = alogs + (k*96 + d)*8;
    #pragma unroll
    for (int n = 0; n < 8; n++){
        float a = -__expf(arow[n]); aN[n] = a;
        fast = fast && (fabsf(a + (float)(n+1)) < 1e-3f*(float)(n+1));
    }
    float h[8];
    {
        int ib = (bk*NCH + chunk)*8*96 + d;
        #pragma unroll
        for (int n = 0; n < 8; n++) h[n] = g_hin[ib + n*96];
    }
    __syncthreads();
    int base2 = ((bk*NCH + chunk)*96 + d)*CS;
    int ybase = (bk*LL + l0)*96 + d;
    if (fast){
        const float4* eu4 = (const float4*)(g_eu + base2);
        float4 buf[4];
        #pragma unroll
        for (int i = 0; i < 4; i++) buf[i] = eu4[i];
        for (int grp = 0; grp < NGRP; grp++){
            float4 nxt[4];
            if (grp + 1 < NGRP){
                #pragma unroll
                for (int i = 0; i < 4; i++) nxt[i] = eu4[(grp+1)*4 + i];
            }
            #pragma unroll
            for (int i = 0; i < 4; i++){
                int s = grp*8 + i*2;
                {   float e1 = buf[i].x, u = buf[i].y;
                    float P[8]; POWER_TREE(e1, P);
                    float4 b0 = *(const float4*)(bS + s*8);
                    float4 b1 = *(const float4*)(bS + s*8 + 4);
                    h[0]=fmaf(P[0],h[0],u*b0.x); h[1]=fmaf(P[1],h[1],u*b0.y);
                    h[2]=fmaf(P[2],h[2],u*b0.z); h[3]=fmaf(P[3],h[3],u*b0.w);
                    h[4]=fmaf(P[4],h[4],u*b1.x); h[5]=fmaf(P[5],h[5],u*b1.y);
                    h[6]=fmaf(P[6],h[6],u*b1.z); h[7]=fmaf(P[7],h[7],u*b1.w);
                    float4 c0 = *(const float4*)(cS + s*8);
                    float4 c1 = *(const float4*)(cS + s*8 + 4);
                    float a0 = h[0]*c0.x, a1 = h[1]*c0.y;
                    a0 = fmaf(h[2], c0.z, a0);  a1 = fmaf(h[3], c0.w, a1);
                    a0 = fmaf(h[4], c1.x, a0);  a1 = fmaf(h[5], c1.y, a1);
                    a0 = fmaf(h[6], c1.z, a0);  a1 = fmaf(h[7], c1.w, a1);
                    g_y[ybase + s*96] = a0 + a1;
                }
                {   float e1 = buf[i].z, u = buf[i].w;
                    float P[8]; POWER_TREE(e1, P);
                    float4 b0 = *(const float4*)(bS + (s+1)*8);
                    float4 b1 = *(const float4*)(bS + (s+1)*8 + 4);
                    h[0]=fmaf(P[0],h[0],u*b0.x); h[1]=fmaf(P[1],h[1],u*b0.y);
                    h[2]=fmaf(P[2],h[2],u*b0.z); h[3]=fmaf(P[3],h[3],u*b0.w);
                    h[4]=fmaf(P[4],h[4],u*b1.x); h[5]=fmaf(P[5],h[5],u*b1.y);
                    h[6]=fmaf(P[6],h[6],u*b1.z); h[7]=fmaf(P[7],h[7],u*b1.w);
                    float4 c0 = *(const float4*)(cS + (s+1)*8);
                    float4 c1 = *(const float4*)(cS + (s+1)*8 + 4);
                    float a0 = h[0]*c0.x, a1 = h[1]*c0.y;
                    a0 = fmaf(h[2], c0.z, a0);  a1 = fmaf(h[3], c0.w, a1);
                    a0 = fmaf(h[4], c1.x, a0);  a1 = fmaf(h[5], c1.y, a1);
                    a0 = fmaf(h[6], c1.z, a0);  a1 = fmaf(h[7], c1.w, a1);
                    g_y[ybase + (s+1)*96] = a0 + a1;
                }
            }
            #pragma unroll
            for (int i = 0; i < 4; i++) buf[i] = nxt[i];
        }
    } else {
        const float2* eu2 = g_eu + base2;
        for (int s = 0; s < CS; s++){
            float2 eu = eu2[s];
            float delta = -__logf(fmaxf(eu.x, 1e-37f));
            float acc = 0.f;
            #pragma unroll
            for (int n = 0; n < 8; n++){
                float dA = __expf(delta*aN[n]);
                h[n] = fmaf(dA, h[n], eu.y*bS[s*8 + n]);
                acc  = fmaf(h[n], cS[s*8 + n], acc);
            }
            g_y[ybase + s*96] = acc;
        }
    }
}

// ---------------- K7: merge 4 directions + Ds*x + LN + gate + out-proj ----------------
// grid 256 (= B * 64 rows), block 192. Writes planar (b,c,p).
__global__ void k_out(const float* __restrict__ Ds, const float* __restrict__ lng,
                      const float* __restrict__ lnb, const float* __restrict__ ow,
                      float* __restrict__ dst){
    __shared__ __align__(16) float yoT[96*68];   // [d][m]
    __shared__ float meanS[64], rstdS[64];
    int t  = threadIdx.x;
    int b  = blockIdx.x >> 6;
    int p0 = (blockIdx.x & 63) << 6;
    for (int i = t; i < 6144; i += 192){
        int d = i % 96, m = i / 96;
        int p  = p0 + m;
        int pt = ((p & 63) << 6) | (p >> 6);
        float ds = __ldg(Ds + d) + __ldg(Ds + 96 + d) + __ldg(Ds + 192 + d) + __ldg(Ds + 288 + d);
        float v = g_y[((b*4 + 0)*LL + p)*96 + d]
                + g_y[((b*4 + 1)*LL + pt)*96 + d]
                + g_y[((b*4 + 2)*LL + (4095 - p))*96 + d]
                + g_y[((b*4 + 3)*LL + (4095 - pt))*96 + d]
                + ds * g_xc[(b*LL + p)*96 + d];
        yoT[d*68 + m] = v;
    }
    __syncthreads();
    if (t < 64){
        float s = 0.f, s2 = 0.f;
        for (int d = 0; d < 96; d++){ float v = yoT[d*68 + t]; s += v; s2 = fmaf(v, v, s2); }
        float mean = s * (1.f/96.f);
        float var  = s2 * (1.f/96.f) - mean*mean;
        meanS[t] = mean;
        rstdS[t] = rsqrtf(var + 1e-5f);
    }
    __syncthreads();
    for (int i = t; i < 6144; i += 192){
        int d = i % 96, m = i / 96;
        float v = (yoT[d*68 + m] - meanS[m]) * rstdS[m] * __ldg(lng + d) + __ldg(lnb + d);
        v *= g_z[(b*LL + p0 + m)*96 + d];
        yoT[d*68 + m] = v;
    }
    __syncthreads();
    {
        int c = t % 96, half = t / 96;
        int m0 = half*32;
        float acc[32];
        #pragma unroll
        for (int m = 0; m < 32; m++) acc[m] = 0.f;
        const float* wrow = ow + c*96;
        for (int d = 0; d < 96; d++){
            float wv = __ldg(wrow + d);
            const float4* yr = (const float4*)(yoT + d*68 + m0);
            #pragma unroll
            for (int m4 = 0; m4 < 8; m4++){
                float4 yv = yr[m4];
                acc[4*m4+0] = fmaf(wv, yv.x, acc[4*m4+0]);
                acc[4*m4+1] = fmaf(wv, yv.y, acc[4*m4+1]);
                acc[4*m4+2] = fmaf(wv, yv.z, acc[4*m4+2]);
                acc[4*m4+3] = fmaf(wv, yv.w, acc[4*m4+3]);
            }
        }
        float* orow = dst + (b*96 + c)*LL + p0 + m0;
        #pragma unroll
        for (int m = 0; m < 32; m++) orow[m] = acc[m];
    }
}

// ---------------- launcher ----------------
extern "C" void kernel_launch(void* const* d_in, const int* in_sizes, int n_in,
                              void* d_out, int out_size){
    (void)in_sizes; (void)n_in; (void)out_size;
    const float* input = (const float*)d_in[0];
    void* midp = nullptr;
    cudaGetSymbolAddress(&midp, g_mid);
    for (int blk = 0; blk < 2; blk++){
        const float* W[11];
        for (int i = 0; i < 11; i++) W[i] = (const float*)d_in[1 + blk*11 + i];
        const float* src = (blk == 0) ? input : (const float*)midp;
        float* dst = (blk == 0) ? (float*)midp : (float*)d_out;
        k_inproj<<<256, 192>>>(src, W[0]);
        k_conv  <<<6144, 256>>>(W[1], W[2]);
        k_xproj <<<2048, 256>>>(W[3], W[4], W[5]);
        k_scan1 <<<dim3(NCH, 16), 96>>>(W[6]);
        k_mid   <<<12, 128>>>();
        k_scan2 <<<dim3(NCH, 16), 96>>>(W[6]);
        k_out   <<<256, 192>>>(W[7], W[8], W[9], W[10], dst);
    }
}

// round 10
// speedup vs baseline: 1.6548x; 1.0980x over previous
#include <cuda_runtime.h>

#define BATCH 4
#define DD 96
#define NS 8
#define KD 4
#define LL 4096
#define CS 64     // chunk size (steps)
#define NCH 64    // number of chunks = LL/CS
#define NGRP 8    // CS/8

// ---------------- scratch (device globals; no allocation allowed) ----------------
__device__ float  g_xa [BATCH*LL*DD];
__device__ float  g_z  [BATCH*LL*DD];          // silu(z)
__device__ float  g_xc [BATCH*LL*DD];          // conv+silu output
__device__ float2 g_eu [BATCH*KD*LL*DD];       // {e1,u} ; layout [(bk*NCH+ch)*96+d]*CS + s
__device__ float  g_bB [BATCH*KD*LL*8];        // B
__device__ float  g_bC [BATCH*KD*LL*8];        // C
__device__ float  g_y  [BATCH*KD*LL*DD];       // scan output per direction
__device__ float  g_hp [BATCH*KD*NCH*16*DD];   // per-chunk {h_end(8),P(8)} comp-major [..][comp][d]
__device__ float  g_hin[BATCH*KD*NCH*8*DD];    // per-chunk incoming state comp-major
__device__ float  g_mid[BATCH*DD*LL];          // inter-block activation, planar (b,c,p)

// ---------------- K1: in-projection GEMM (planar (b,c,p) -> xa, silu(z)) --------
// grid 256 (= B * L/64), block 192, dynamic smem.
// Weights staged in pad-97 smem: conflict-free reads, coalesced staging.
__global__ void __launch_bounds__(192) k_inproj(const float* __restrict__ src,
                                                const float* __restrict__ in_w){
    extern __shared__ __align__(16) float dyn[];
    float* sm = dyn;              // 64*97 : X[96][64] then OUT[64][97]
    float* wS = dyn + 64*97;      // 192*97
    int b  = blockIdx.x >> 6;
    int p0 = (blockIdx.x & 63) << 6;
    int t  = threadIdx.x;
    for (int i = t; i < 96*64; i += 192){
        int c = i >> 6, m = i & 63;
        sm[i] = src[((b*96 + c) << 12) + p0 + m];
    }
    for (int i = t; i < 192*96; i += 192){
        int row = i / 96, col = i - row*96;
        wS[row*97 + col] = in_w[i];
    }
    __syncthreads();
    float acc[64];
    #pragma unroll
    for (int m = 0; m < 64; m++) acc[m] = 0.f;
    const float* wrow = wS + t*97;
    for (int c = 0; c < 96; c++){
        float wv = wrow[c];
        const float4* xr = (const float4*)(sm + (c<<6));
        #pragma unroll
        for (int m4 = 0; m4 < 16; m4++){
            float4 xv = xr[m4];
            acc[4*m4+0] = fmaf(wv, xv.x, acc[4*m4+0]);
            acc[4*m4+1] = fmaf(wv, xv.y, acc[4*m4+1]);
            acc[4*m4+2] = fmaf(wv, xv.z, acc[4*m4+2]);
            acc[4*m4+3] = fmaf(wv, xv.w, acc[4*m4+3]);
        }
    }
    __syncthreads();
    if (t < 96){
        #pragma unroll
        for (int m = 0; m < 64; m++) sm[m*97 + t] = acc[m];
    }
    __syncthreads();
    for (int i = t; i < 64*96; i += 192){
        int m = i/96, d = i - m*96;
        g_xa[(b*LL + p0 + m)*96 + d] = sm[m*97 + d];
    }
    __syncthreads();
    if (t >= 96){
        #pragma unroll
        for (int m = 0; m < 64; m++) sm[m*97 + (t-96)] = acc[m];
    }
    __syncthreads();
    for (int i = t; i < 64*96; i += 192){
        int m = i/96, d = i - m*96;
        float v = sm[m*97 + d];
        g_z[(b*LL + p0 + m)*96 + d] = v * __fdividef(1.f, 1.f + __expf(-v));
    }
}

// ---------------- K2: depthwise 3x3 conv + bias + silu ----------------
// grid 6144, block 256 : one thread per (b,p,d)
__global__ void k_conv(const float* __restrict__ cw, const float* __restrict__ cb){
    int idx = blockIdx.x*256 + threadIdx.x;
    int d  = idx % 96;
    int pp = idx / 96;
    int p  = pp & 4095, b = pp >> 12;
    int h  = p >> 6,    w = p & 63;
    const float* wt = cw + d*9;
    float a = 0.f;
    #pragma unroll
    for (int i = 0; i < 3; i++){
        int hh = h + i - 1;
        if ((unsigned)hh < 64u){
            #pragma unroll
            for (int j = 0; j < 3; j++){
                int ww = w + j - 1;
                if ((unsigned)ww < 64u)
                    a = fmaf(__ldg(wt + i*3 + j), g_xa[(b*LL + (hh<<6) + ww)*96 + d], a);
            }
        }
    }
    a += __ldg(cb + d);
    g_xc[idx] = a * __fdividef(1.f, 1.f + __expf(-a));
}

// direction index map: scan step l of direction k reads spatial position perm(k,l)
__device__ __forceinline__ int perm_idx(int k, int l){
    if (k == 0) return l;
    if (k == 1) return ((l & 63) << 6) | (l >> 6);
    if (k == 2) return 4095 - l;
    int m = 4095 - l; return ((m & 63) << 6) | (m >> 6);
}

// ---------------- K3: x-projection + dt + softplus precompute ----------------
// grid 2048 (= B*K * L/32), block 256
// xvT is [d][m] with pad 33 -> conflict-free LDS everywhere; xp reads are warp-broadcast.
__global__ void __launch_bounds__(256) k_xproj(const float* __restrict__ xpw,
                        const float* __restrict__ dtw, const float* __restrict__ dtb){
    __shared__ float xvT[96*33];       // [d][m]
    __shared__ float xdbl[32*25];
    __shared__ float xpS[22*96];
    __shared__ float dtwS[96*6];
    __shared__ float dtbS[96];
    int t   = threadIdx.x;
    int g   = blockIdx.x;
    int seg = g & 127, bk = g >> 7;
    int b   = bk >> 2,  k = bk & 3;
    int l0  = seg << 5;
    for (int i = t; i < 22*96; i += 256) xpS[i]  = xpw[k*22*96 + i];
    for (int i = t; i < 96*6;  i += 256) dtwS[i] = dtw[k*96*6 + i];
    if (t < 96) dtbS[t] = dtb[k*96 + t];
    for (int i = t; i < 32*96; i += 256){
        int m = i/96, d = i - m*96;
        int p = perm_idx(k, l0 + m);
        xvT[d*33 + m] = g_xc[(b*LL + p)*96 + d];
    }
    __syncthreads();
    // GEMM: 22 channels x 32 positions. lane = m (conflict-free xvT), warp-uniform c (broadcast xpS).
    {
        int m  = t & 31;
        int c0 = t >> 5;            // 0..7
        int c1 = c0 + 8;            // 8..15
        int c2 = c0 + 16;           // 16..23 (valid if < 22)
        float a0 = 0.f, a1 = 0.f, a2 = 0.f;
        const float* xp0 = xpS + c0*96;
        const float* xp1 = xpS + c1*96;
        const float* xp2 = xpS + (c2 < 22 ? c2 : 0)*96;
        #pragma unroll 4
        for (int d = 0; d < 96; d++){
            float xv = xvT[d*33 + m];
            a0 = fmaf(xp0[d], xv, a0);
            a1 = fmaf(xp1[d], xv, a1);
            a2 = fmaf(xp2[d], xv, a2);
        }
        xdbl[m*25 + c0] = a0;
        xdbl[m*25 + c1] = a1;
        if (c2 < 22) xdbl[m*25 + c2] = a2;
    }
    __syncthreads();
    // chunk-major eu write: chunk = seg>>1, base step = (seg&1)*32
    int chunk = seg >> 1, s0 = (seg & 1) << 5;
    for (int j = t; j < 32*96; j += 256){
        int m = j & 31, d = j >> 5;        // m fastest -> contiguous stores
        float s = dtbS[d];
        #pragma unroll
        for (int r = 0; r < 6; r++) s = fmaf(dtwS[d*6 + r], xdbl[m*25 + r], s);
        float et    = __expf(fminf(s, 60.f));
        float delta = (s > 15.f) ? s : __logf(1.f + et);   // softplus
        float e1    = __fdividef(1.f, 1.f + et);           // exp(-softplus(s))
        g_eu[((bk*NCH + chunk)*96 + d)*CS + s0 + m] = make_float2(e1, delta * xvT[d*33 + m]);
    }
    {
        int m = t >> 3, i = t & 7;   // 256 threads cover 32*8 exactly
        g_bB[(bk*LL + l0 + m)*8 + i] = xdbl[m*25 + 6 + i];
        g_bC[(bk*LL + l0 + m)*8 + i] = xdbl[m*25 + 14 + i];
    }
}

// log-depth powers e1^1..e1^8
#define POWER_TREE(e1, P)                                     \
    { P[0]=e1; P[1]=e1*e1; P[3]=P[1]*P[1]; P[2]=P[1]*e1;      \
      P[4]=P[3]*e1; P[5]=P[3]*P[1]; P[6]=P[3]*P[2]; P[7]=P[3]*P[3]; }

// ---------------- K4: scan pass 1 (per-chunk h_end and A-product) ----------------
// grid (NCH, 16), block 96
__global__ void __launch_bounds__(96) k_scan1(const float* __restrict__ alogs){
    __shared__ __align__(16) float bS[CS*8];
    int chunk = blockIdx.x, bk = blockIdx.y;
    int k = bk & 3;
    int d = threadIdx.x;
    int l0 = chunk*CS;
    for (int i = d; i < CS*8; i += 96) bS[i] = g_bB[(bk*LL + l0)*8 + i];
    float aN[8]; bool fast = true;
    const float* arow = alogs + (k*96 + d)*8;
    #pragma unroll
    for (int n = 0; n < 8; n++){
        float a = -__expf(arow[n]); aN[n] = a;
        fast = fast && (fabsf(a + (float)(n+1)) < 1e-3f*(float)(n+1));
    }
    __syncthreads();
    float h[8];
    #pragma unroll
    for (int n = 0; n < 8; n++) h[n] = 0.f;
    int base2 = ((bk*NCH + chunk)*96 + d)*CS;
    int ob = (bk*NCH + chunk)*16*96 + d;    // comp-major: +comp*96
    if (fast){
        const float4* eu4 = (const float4*)(g_eu + base2);  // 2 steps per float4
        float4 buf[4];
        #pragma unroll
        for (int i = 0; i < 4; i++) buf[i] = eu4[i];
        float q = 1.f;
        for (int grp = 0; grp < NGRP; grp++){
            float4 nxt[4];
            if (grp + 1 < NGRP){
                #pragma unroll
                for (int i = 0; i < 4; i++) nxt[i] = eu4[(grp+1)*4 + i];
            }
            #pragma unroll
            for (int i = 0; i < 4; i++){
                int s = grp*8 + i*2;
                {   float e1 = buf[i].x, u = buf[i].y;
                    float P[8]; POWER_TREE(e1, P);
                    q *= e1;
                    float4 b0 = *(const float4*)(bS + s*8);
                    float4 b1 = *(const float4*)(bS + s*8 + 4);
                    h[0]=fmaf(P[0],h[0],u*b0.x); h[1]=fmaf(P[1],h[1],u*b0.y);
                    h[2]=fmaf(P[2],h[2],u*b0.z); h[3]=fmaf(P[3],h[3],u*b0.w);
                    h[4]=fmaf(P[4],h[4],u*b1.x); h[5]=fmaf(P[5],h[5],u*b1.y);
                    h[6]=fmaf(P[6],h[6],u*b1.z); h[7]=fmaf(P[7],h[7],u*b1.w);
                }
                {   float e1 = buf[i].z, u = buf[i].w;
                    float P[8]; POWER_TREE(e1, P);
                    q *= e1;
                    float4 b0 = *(const float4*)(bS + (s+1)*8);
                    float4 b1 = *(const float4*)(bS + (s+1)*8 + 4);
                    h[0]=fmaf(P[0],h[0],u*b0.x); h[1]=fmaf(P[1],h[1],u*b0.y);
                    h[2]=fmaf(P[2],h[2],u*b0.z); h[3]=fmaf(P[3],h[3],u*b0.w);
                    h[4]=fmaf(P[4],h[4],u*b1.x); h[5]=fmaf(P[5],h[5],u*b1.y);
                    h[6]=fmaf(P[6],h[6],u*b1.z); h[7]=fmaf(P[7],h[7],u*b1.w);
                }
            }
            #pragma unroll
            for (int i = 0; i < 4; i++) buf[i] = nxt[i];
        }
        float P[8]; POWER_TREE(q, P);
        #pragma unroll
        for (int n = 0; n < 8; n++){ g_hp[ob + n*96] = h[n]; g_hp[ob + (8+n)*96] = P[n]; }
    } else {
        const float2* eu2 = g_eu + base2;
        float P[8];
        #pragma unroll
        for (int n = 0; n < 8; n++) P[n] = 1.f;
        for (int s = 0; s < CS; s++){
            float2 eu = eu2[s];
            float delta = -__logf(fmaxf(eu.x, 1e-37f));
            #pragma unroll
            for (int n = 0; n < 8; n++){
                float dA = __expf(delta*aN[n]);
                h[n] = fmaf(dA, h[n], eu.y*bS[s*8 + n]);
                P[n] *= dA;
            }
        }
        #pragma unroll
        for (int n = 0; n < 8; n++){ g_hp[ob + n*96] = h[n]; g_hp[ob + (8+n)*96] = P[n]; }
    }
}

// ---------------- K5: chunk-boundary scan (tiny, coalesced + prefetched) ----------------
__global__ void k_mid(){
    int t = blockIdx.x*128 + threadIdx.x;
    if (t >= 16*96) return;
    int bk = t/96, d = t - bk*96;
    float h[8];
    #pragma unroll
    for (int n = 0; n < 8; n++) h[n] = 0.f;
    float cur[16];
    {
        int hb = (bk*NCH)*16*96 + d;
        #pragma unroll
        for (int i = 0; i < 16; i++) cur[i] = g_hp[hb + i*96];
    }
    for (int c = 0; c < NCH; c++){
        float nxt[16];
        if (c + 1 < NCH){
            int hb = (bk*NCH + c + 1)*16*96 + d;
            #pragma unroll
            for (int i = 0; i < 16; i++) nxt[i] = g_hp[hb + i*96];
        }
        int ib = (bk*NCH + c)*8*96 + d;
        #pragma unroll
        for (int n = 0; n < 8; n++) g_hin[ib + n*96] = h[n];
        #pragma unroll
        for (int n = 0; n < 8; n++) h[n] = fmaf(cur[8+n], h[n], cur[n]);
        #pragma unroll
        for (int i = 0; i < 16; i++) cur[i] = nxt[i];
    }
}

// ---------------- K6: scan pass 2 (seeded recompute, emit y) ----------------
__global__ void __launch_bounds__(96) k_scan2(const float* __restrict__ alogs){
    __shared__ __align__(16) float bS[CS*8];
    __shared__ __align__(16) float cS[CS*8];
    int chunk = blockIdx.x, bk = blockIdx.y;
    int k = bk & 3;
    int d = threadIdx.x;
    int l0 = chunk*CS;
    for (int i = d; i < CS*8; i += 96){
        bS[i] = g_bB[(bk*LL + l0)*8 + i];
        cS[i] = g_bC[(bk*LL + l0)*8 + i];
    }
    float aN[8]; bool fast = true;
    const float* arow = alogs + (k*96 + d)*8;
    #pragma unroll
    for (int n = 0; n < 8; n++){
        float a = -__expf(arow[n]); aN[n] = a;
        fast = fast && (fabsf(a + (float)(n+1)) < 1e-3f*(float)(n+1));
    }
    float h[8];
    {
        int ib = (bk*NCH + chunk)*8*96 + d;
        #pragma unroll
        for (int n = 0; n < 8; n++) h[n] = g_hin[ib + n*96];
    }
    __syncthreads();
    int base2 = ((bk*NCH + chunk)*96 + d)*CS;
    int ybase = (bk*LL + l0)*96 + d;
    if (fast){
        const float4* eu4 = (const float4*)(g_eu + base2);
        float4 buf[4];
        #pragma unroll
        for (int i = 0; i < 4; i++) buf[i] = eu4[i];
        for (int grp = 0; grp < NGRP; grp++){
            float4 nxt[4];
            if (grp + 1 < NGRP){
                #pragma unroll
                for (int i = 0; i < 4; i++) nxt[i] = eu4[(grp+1)*4 + i];
            }
            #pragma unroll
            for (int i = 0; i < 4; i++){
                int s = grp*8 + i*2;
                {   float e1 = buf[i].x, u = buf[i].y;
                    float P[8]; POWER_TREE(e1, P);
                    float4 b0 = *(const float4*)(bS + s*8);
                    float4 b1 = *(const float4*)(bS + s*8 + 4);
                    h[0]=fmaf(P[0],h[0],u*b0.x); h[1]=fmaf(P[1],h[1],u*b0.y);
                    h[2]=fmaf(P[2],h[2],u*b0.z); h[3]=fmaf(P[3],h[3],u*b0.w);
                    h[4]=fmaf(P[4],h[4],u*b1.x); h[5]=fmaf(P[5],h[5],u*b1.y);
                    h[6]=fmaf(P[6],h[6],u*b1.z); h[7]=fmaf(P[7],h[7],u*b1.w);
                    float4 c0 = *(const float4*)(cS + s*8);
                    float4 c1 = *(const float4*)(cS + s*8 + 4);
                    float a0 = h[0]*c0.x, a1 = h[1]*c0.y;
                    a0 = fmaf(h[2], c0.z, a0);  a1 = fmaf(h[3], c0.w, a1);
                    a0 = fmaf(h[4], c1.x, a0);  a1 = fmaf(h[5], c1.y, a1);
                    a0 = fmaf(h[6], c1.z, a0);  a1 = fmaf(h[7], c1.w, a1);
                    g_y[ybase + s*96] = a0 + a1;
                }
                {   float e1 = buf[i].z, u = buf[i].w;
                    float P[8]; POWER_TREE(e1, P);
                    float4 b0 = *(const float4*)(bS + (s+1)*8);
                    float4 b1 = *(const float4*)(bS + (s+1)*8 + 4);
                    h[0]=fmaf(P[0],h[0],u*b0.x); h[1]=fmaf(P[1],h[1],u*b0.y);
                    h[2]=fmaf(P[2],h[2],u*b0.z); h[3]=fmaf(P[3],h[3],u*b0.w);
                    h[4]=fmaf(P[4],h[4],u*b1.x); h[5]=fmaf(P[5],h[5],u*b1.y);
                    h[6]=fmaf(P[6],h[6],u*b1.z); h[7]=fmaf(P[7],h[7],u*b1.w);
                    float4 c0 = *(const float4*)(cS + (s+1)*8);
                    float4 c1 = *(const float4*)(cS + (s+1)*8 + 4);
                    float a0 = h[0]*c0.x, a1 = h[1]*c0.y;
                    a0 = fmaf(h[2], c0.z, a0);  a1 = fmaf(h[3], c0.w, a1);
                    a0 = fmaf(h[4], c1.x, a0);  a1 = fmaf(h[5], c1.y, a1);
                    a0 = fmaf(h[6], c1.z, a0);  a1 = fmaf(h[7], c1.w, a1);
                    g_y[ybase + (s+1)*96] = a0 + a1;
                }
            }
            #pragma unroll
            for (int i = 0; i < 4; i++) buf[i] = nxt[i];
        }
    } else {
        const float2* eu2 = g_eu + base2;
        for (int s = 0; s < CS; s++){
            float2 eu = eu2[s];
            float delta = -__logf(fmaxf(eu.x, 1e-37f));
            float acc = 0.f;
            #pragma unroll
            for (int n = 0; n < 8; n++){
                float dA = __expf(delta*aN[n]);
                h[n] = fmaf(dA, h[n], eu.y*bS[s*8 + n]);
                acc  = fmaf(h[n], cS[s*8 + n], acc);
            }
            g_y[ybase + s*96] = acc;
        }
    }
}

// ---------------- K7: merge 4 directions + Ds*x + LN + gate + out-proj ----------------
// grid 256 (= B * 64 rows), block 192, dynamic smem. Writes planar (b,c,p).
__global__ void __launch_bounds__(192) k_out(const float* __restrict__ Ds,
                      const float* __restrict__ lng,
                      const float* __restrict__ lnb, const float* __restrict__ ow,
                      float* __restrict__ dst){
    extern __shared__ __align__(16) float dyn[];
    float* yoT   = dyn;                 // 96*68 : [d][m]
    float* wS    = dyn + 96*68;         // 96*97
    float* meanS = wS + 96*97;          // 64
    float* rstdS = meanS + 64;          // 64
    int t  = threadIdx.x;
    int b  = blockIdx.x >> 6;
    int p0 = (blockIdx.x & 63) << 6;
    for (int i = t; i < 96*96; i += 192){
        int c = i / 96, d = i - c*96;
        wS[c*97 + d] = ow[i];
    }
    for (int i = t; i < 6144; i += 192){
        int d = i % 96, m = i / 96;
        int p  = p0 + m;
        int pt = ((p & 63) << 6) | (p >> 6);
        float ds = __ldg(Ds + d) + __ldg(Ds + 96 + d) + __ldg(Ds + 192 + d) + __ldg(Ds + 288 + d);
        float v = g_y[((b*4 + 0)*LL + p)*96 + d]
                + g_y[((b*4 + 1)*LL + pt)*96 + d]
                + g_y[((b*4 + 2)*LL + (4095 - p))*96 + d]
                + g_y[((b*4 + 3)*LL + (4095 - pt))*96 + d]
                + ds * g_xc[(b*LL + p)*96 + d];
        yoT[d*68 + m] = v;
    }
    __syncthreads();
    if (t < 64){
        float s = 0.f, s2 = 0.f;
        for (int d = 0; d < 96; d++){ float v = yoT[d*68 + t]; s += v; s2 = fmaf(v, v, s2); }
        float mean = s * (1.f/96.f);
        float var  = s2 * (1.f/96.f) - mean*mean;
        meanS[t] = mean;
        rstdS[t] = rsqrtf(var + 1e-5f);
    }
    __syncthreads();
    for (int i = t; i < 6144; i += 192){
        int d = i % 96, m = i / 96;
        float v = (yoT[d*68 + m] - meanS[m]) * rstdS[m] * __ldg(lng + d) + __ldg(lnb + d);
        v *= g_z[(b*LL + p0 + m)*96 + d];
        yoT[d*68 + m] = v;
    }
    __syncthreads();
    {
        int c = t % 96, half = t / 96;
        int m0 = half*32;
        float acc[32];
        #pragma unroll
        for (int m = 0; m < 32; m++) acc[m] = 0.f;
        const float* wrow = wS + c*97;
        for (int d = 0; d < 96; d++){
            float wv = wrow[d];
            const float4* yr = (const float4*)(yoT + d*68 + m0);
            #pragma unroll
            for (int m4 = 0; m4 < 8; m4++){
                float4 yv = yr[m4];
                acc[4*m4+0] = fmaf(wv, yv.x, acc[4*m4+0]);
                acc[4*m4+1] = fmaf(wv, yv.y, acc[4*m4+1]);
                acc[4*m4+2] = fmaf(wv, yv.z, acc[4*m4+2]);
                acc[4*m4+3] = fmaf(wv, yv.w, acc[4*m4+3]);
            }
        }
        float* orow = dst + (b*96 + c)*LL + p0 + m0;
        #pragma unroll
        for (int m = 0; m < 32; m++) orow[m] = acc[m];
    }
}

// ---------------- launcher ----------------
extern "C" void kernel_launch(void* const* d_in, const int* in_sizes, int n_in,
                              void* d_out, int out_size){
    (void)in_sizes; (void)n_in; (void)out_size;
    const int SM_INPROJ = (64*97 + 192*97) * 4;          // 99328 B
    const int SM_OUT    = (96*68 + 96*97 + 128) * 4;     // 64384 B
    cudaFuncSetAttribute(k_inproj, cudaFuncAttributeMaxDynamicSharedMemorySize, SM_INPROJ);
    cudaFuncSetAttribute(k_out,    cudaFuncAttributeMaxDynamicSharedMemorySize, SM_OUT);
    const float* input = (const float*)d_in[0];
    void* midp = nullptr;
    cudaGetSymbolAddress(&midp, g_mid);
    for (int blk = 0; blk < 2; blk++){
        const float* W[11];
        for (int i = 0; i < 11; i++) W[i] = (const float*)d_in[1 + blk*11 + i];
        const float* src = (blk == 0) ? input : (const float*)midp;
        float* dst = (blk == 0) ? (float*)midp : (float*)d_out;
        k_inproj<<<256, 192, SM_INPROJ>>>(src, W[0]);
        k_conv  <<<6144, 256>>>(W[1], W[2]);
        k_xproj <<<2048, 256>>>(W[3], W[4], W[5]);
        k_scan1 <<<dim3(NCH, 16), 96>>>(W[6]);
        k_mid   <<<12, 128>>>();
        k_scan2 <<<dim3(NCH, 16), 96>>>(W[6]);
        k_out   <<<256, 192, SM_OUT>>>(W[7], W[8], W[9], W[10], dst);
    }
}

// round 12
// speedup vs baseline: 1.6799x; 1.0152x over previous
#include <cuda_runtime.h>

#define BATCH 4
#define DD 96
#define NS 8
#define KD 4
#define LL 4096
#define CS 64     // chunk size (steps)
#define NCH 64    // number of chunks = LL/CS
#define NGRP 8    // CS/8

// ---------------- scratch (device globals; no allocation allowed) ----------------
__device__ float  g_xa [BATCH*LL*DD];
__device__ float  g_z  [BATCH*LL*DD];          // silu(z)
__device__ float  g_xc [BATCH*LL*DD];          // conv+silu output
__device__ float2 g_eu [BATCH*KD*LL*DD];       // {e1,u} ; layout [(bk*NCH+ch)*96+d]*CS + s
__device__ float  g_bB [BATCH*KD*LL*8];        // B
__device__ float  g_bC [BATCH*KD*LL*8];        // C
__device__ float  g_y  [BATCH*KD*LL*DD];       // scan output per direction
__device__ float  g_hp [BATCH*KD*NCH*16*DD];   // per-chunk {h_end(8),P(8)} comp-major [..][comp][d]
__device__ float  g_hin[BATCH*KD*NCH*8*DD];    // per-chunk incoming state comp-major
__device__ float  g_mid[BATCH*DD*LL];          // inter-block activation, planar (b,c,p)

// ---------------- K1: in-projection GEMM (planar (b,c,p) -> xa, silu(z)) --------
// grid 256 (= B * L/64), block 192, dynamic smem.
__global__ void __launch_bounds__(192) k_inproj(const float* __restrict__ src,
                                                const float* __restrict__ in_w){
    extern __shared__ __align__(16) float dyn[];
    float* sm = dyn;              // 64*97 : X[96][64] then OUT[64][97]
    float* wS = dyn + 64*97;      // 192*97
    int b  = blockIdx.x >> 6;
    int p0 = (blockIdx.x & 63) << 6;
    int t  = threadIdx.x;
    for (int i = t; i < 96*64; i += 192){
        int c = i >> 6, m = i & 63;
        sm[i] = src[((b*96 + c) << 12) + p0 + m];
    }
    for (int i = t; i < 192*96; i += 192){
        int row = i / 96, col = i - row*96;
        wS[row*97 + col] = in_w[i];
    }
    __syncthreads();
    float acc[64];
    #pragma unroll
    for (int m = 0; m < 64; m++) acc[m] = 0.f;
    const float* wrow = wS + t*97;
    for (int c = 0; c < 96; c++){
        float wv = wrow[c];
        const float4* xr = (const float4*)(sm + (c<<6));
        #pragma unroll
        for (int m4 = 0; m4 < 16; m4++){
            float4 xv = xr[m4];
            acc[4*m4+0] = fmaf(wv, xv.x, acc[4*m4+0]);
            acc[4*m4+1] = fmaf(wv, xv.y, acc[4*m4+1]);
            acc[4*m4+2] = fmaf(wv, xv.z, acc[4*m4+2]);
            acc[4*m4+3] = fmaf(wv, xv.w, acc[4*m4+3]);
        }
    }
    __syncthreads();
    if (t < 96){
        #pragma unroll
        for (int m = 0; m < 64; m++) sm[m*97 + t] = acc[m];
    }
    __syncthreads();
    for (int i = t; i < 64*96; i += 192){
        int m = i/96, d = i - m*96;
        g_xa[(b*LL + p0 + m)*96 + d] = sm[m*97 + d];
    }
    __syncthreads();
    if (t >= 96){
        #pragma unroll
        for (int m = 0; m < 64; m++) sm[m*97 + (t-96)] = acc[m];
    }
    __syncthreads();
    for (int i = t; i < 64*96; i += 192){
        int m = i/96, d = i - m*96;
        float v = sm[m*97 + d];
        g_z[(b*LL + p0 + m)*96 + d] = v * __fdividef(1.f, 1.f + __expf(-v));
    }
}

// ---------------- K2: depthwise 3x3 conv + bias + silu ----------------
// grid 6144, block 256 : one thread per (b,p,d)
__global__ void k_conv(const float* __restrict__ cw, const float* __restrict__ cb){
    int idx = blockIdx.x*256 + threadIdx.x;
    int d  = idx % 96;
    int pp = idx / 96;
    int p  = pp & 4095, b = pp >> 12;
    int h  = p >> 6,    w = p & 63;
    const float* wt = cw + d*9;
    float a = 0.f;
    #pragma unroll
    for (int i = 0; i < 3; i++){
        int hh = h + i - 1;
        if ((unsigned)hh < 64u){
            #pragma unroll
            for (int j = 0; j < 3; j++){
                int ww = w + j - 1;
                if ((unsigned)ww < 64u)
                    a = fmaf(__ldg(wt + i*3 + j), g_xa[(b*LL + (hh<<6) + ww)*96 + d], a);
            }
        }
    }
    a += __ldg(cb + d);
    g_xc[idx] = a * __fdividef(1.f, 1.f + __expf(-a));
}

// direction index map: scan step l of direction k reads spatial position perm(k,l)
__device__ __forceinline__ int perm_idx(int k, int l){
    if (k == 0) return l;
    if (k == 1) return ((l & 63) << 6) | (l >> 6);
    if (k == 2) return 4095 - l;
    int m = 4095 - l; return ((m & 63) << 6) | (m >> 6);
}

// ---------------- K3: x-projection + dt + softplus precompute ----------------
// grid 1024 (= B*K * NCH), block 256. 64 positions (= one chunk) per CTA.
// xvT [d][m] pad 65 -> conflict-free; warp-uniform channels -> broadcast xpS.
__global__ void __launch_bounds__(256) k_xproj(const float* __restrict__ xpw,
                        const float* __restrict__ dtw, const float* __restrict__ dtb){
    __shared__ float xvT[96*65];       // [d][m] 24.96 KB
    __shared__ float xdbl[64*25];
    __shared__ float xpS[22*96];
    __shared__ float dtwS[96*6];
    __shared__ float dtbS[96];
    int t   = threadIdx.x;
    int g   = blockIdx.x;
    int seg = g & 63, bk = g >> 6;     // seg == chunk
    int b   = bk >> 2,  k = bk & 3;
    int l0  = seg << 6;
    for (int i = t; i < 22*96; i += 256) xpS[i]  = xpw[k*22*96 + i];
    for (int i = t; i < 96*6;  i += 256) dtwS[i] = dtw[k*96*6 + i];
    if (t < 96) dtbS[t] = dtb[k*96 + t];
    for (int i = t; i < 64*96; i += 256){
        int m = i/96, d = i - m*96;
        int p = perm_idx(k, l0 + m);
        xvT[d*65 + m] = g_xc[(b*LL + p)*96 + d];
    }
    __syncthreads();
    // GEMM: 22 channels x 64 positions. lane = m (conflict-free), warp-uniform c (broadcast).
    {
        int m  = t & 63;
        int c0 = t >> 6;               // 0..3
        float a[6];
        #pragma unroll
        for (int j = 0; j < 6; j++) a[j] = 0.f;
        #pragma unroll 2
        for (int d = 0; d < 96; d++){
            float xv = xvT[d*65 + m];
            const float* xpd = xpS + d;
            #pragma unroll
            for (int j = 0; j < 6; j++){
                int c = c0 + 4*j;
                if (c < 22) a[j] = fmaf(xpd[c*96], xv, a[j]);
            }
        }
        #pragma unroll
        for (int j = 0; j < 6; j++){
            int c = c0 + 4*j;
            if (c < 22) xdbl[m*25 + c] = a[j];
        }
    }
    __syncthreads();
    for (int j = t; j < 64*96; j += 256){
        int m = j & 63, d = j >> 6;        // m fastest -> contiguous stores
        float s = dtbS[d];
        #pragma unroll
        for (int r = 0; r < 6; r++) s = fmaf(dtwS[d*6 + r], xdbl[m*25 + r], s);
        float et    = __expf(fminf(s, 60.f));
        float delta = (s > 15.f) ? s : __logf(1.f + et);   // softplus
        float e1    = __fdividef(1.f, 1.f + et);           // exp(-softplus(s))
        g_eu[((bk*NCH + seg)*96 + d)*CS + m] = make_float2(e1, delta * xvT[d*65 + m]);
    }
    for (int j = t; j < 64*8; j += 256){
        int m = j >> 3, i = j & 7;
        g_bB[(bk*LL + l0 + m)*8 + i] = xdbl[m*25 + 6 + i];
        g_bC[(bk*LL + l0 + m)*8 + i] = xdbl[m*25 + 14 + i];
    }
}

// log-depth powers e1^1..e1^8
#define POWER_TREE(e1, P)                                     \
    { P[0]=e1; P[1]=e1*e1; P[3]=P[1]*P[1]; P[2]=P[1]*e1;      \
      P[4]=P[3]*e1; P[5]=P[3]*P[1]; P[6]=P[3]*P[2]; P[7]=P[3]*P[3]; }

// ---------------- K4: scan pass 1 (per-chunk h_end and A-product) ----------------
// grid (NCH, 16), block 96
__global__ void __launch_bounds__(96) k_scan1(const float* __restrict__ alogs){
    __shared__ __align__(16) float bS[CS*8];
    int chunk = blockIdx.x, bk = blockIdx.y;
    int k = bk & 3;
    int d = threadIdx.x;
    int l0 = chunk*CS;
    for (int i = d; i < CS*8; i += 96) bS[i] = g_bB[(bk*LL + l0)*8 + i];
    float aN[8]; bool fast = true;
    const float* arow = alogs + (k*96 + d)*8;
    #pragma unroll
    for (int n = 0; n < 8; n++){
        float a = -__expf(arow[n]); aN[n] = a;
        fast = fast && (fabsf(a + (float)(n+1)) < 1e-3f*(float)(n+1));
    }
    __syncthreads();
    float h[8];
    #pragma unroll
    for (int n = 0; n < 8; n++) h[n] = 0.f;
    int base2 = ((bk*NCH + chunk)*96 + d)*CS;
    int ob = (bk*NCH + chunk)*16*96 + d;    // comp-major: +comp*96
    if (fast){
        const float4* eu4 = (const float4*)(g_eu + base2);  // 2 steps per float4
        float4 buf[4];
        #pragma unroll
        for (int i = 0; i < 4; i++) buf[i] = eu4[i];
        float q = 1.f;
        for (int grp = 0; grp < NGRP; grp++){
            float4 nxt[4];
            if (grp + 1 < NGRP){
                #pragma unroll
                for (int i = 0; i < 4; i++) nxt[i] = eu4[(grp+1)*4 + i];
            }
            #pragma unroll
            for (int i = 0; i < 4; i++){
                int s = grp*8 + i*2;
                {   float e1 = buf[i].x, u = buf[i].y;
                    float P[8]; POWER_TREE(e1, P);
                    q *= e1;
                    float4 b0 = *(const float4*)(bS + s*8);
                    float4 b1 = *(const float4*)(bS + s*8 + 4);
                    h[0]=fmaf(P[0],h[0],u*b0.x); h[1]=fmaf(P[1],h[1],u*b0.y);
                    h[2]=fmaf(P[2],h[2],u*b0.z); h[3]=fmaf(P[3],h[3],u*b0.w);
                    h[4]=fmaf(P[4],h[4],u*b1.x); h[5]=fmaf(P[5],h[5],u*b1.y);
                    h[6]=fmaf(P[6],h[6],u*b1.z); h[7]=fmaf(P[7],h[7],u*b1.w);
                }
                {   float e1 = buf[i].z, u = buf[i].w;
                    float P[8]; POWER_TREE(e1, P);
                    q *= e1;
                    float4 b0 = *(const float4*)(bS + (s+1)*8);
                    float4 b1 = *(const float4*)(bS + (s+1)*8 + 4);
                    h[0]=fmaf(P[0],h[0],u*b0.x); h[1]=fmaf(P[1],h[1],u*b0.y);
                    h[2]=fmaf(P[2],h[2],u*b0.z); h[3]=fmaf(P[3],h[3],u*b0.w);
                    h[4]=fmaf(P[4],h[4],u*b1.x); h[5]=fmaf(P[5],h[5],u*b1.y);
                    h[6]=fmaf(P[6],h[6],u*b1.z); h[7]=fmaf(P[7],h[7],u*b1.w);
                }
            }
            #pragma unroll
            for (int i = 0; i < 4; i++) buf[i] = nxt[i];
        }
        float P[8]; POWER_TREE(q, P);
        #pragma unroll
        for (int n = 0; n < 8; n++){ g_hp[ob + n*96] = h[n]; g_hp[ob + (8+n)*96] = P[n]; }
    } else {
        const float2* eu2 = g_eu + base2;
        float P[8];
        #pragma unroll
        for (int n = 0; n < 8; n++) P[n] = 1.f;
        for (int s = 0; s < CS; s++){
            float2 eu = eu2[s];
            float delta = -__logf(fmaxf(eu.x, 1e-37f));
            #pragma unroll
            for (int n = 0; n < 8; n++){
                float dA = __expf(delta*aN[n]);
                h[n] = fmaf(dA, h[n], eu.y*bS[s*8 + n]);
                P[n] *= dA;
            }
        }
        #pragma unroll
        for (int n = 0; n < 8; n++){ g_hp[ob + n*96] = h[n]; g_hp[ob + (8+n)*96] = P[n]; }
    }
}

// ---------------- K5: chunk-boundary scan (tiny, coalesced + prefetched) ----------------
__global__ void k_mid(){
    int t = blockIdx.x*128 + threadIdx.x;
    if (t >= 16*96) return;
    int bk = t/96, d = t - bk*96;
    float h[8];
    #pragma unroll
    for (int n = 0; n < 8; n++) h[n] = 0.f;
    float cur[16];
    {
        int hb = (bk*NCH)*16*96 + d;
        #pragma unroll
        for (int i = 0; i < 16; i++) cur[i] = g_hp[hb + i*96];
    }
    for (int c = 0; c < NCH; c++){
        float nxt[16];
        if (c + 1 < NCH){
            int hb = (bk*NCH + c + 1)*16*96 + d;
            #pragma unroll
            for (int i = 0; i < 16; i++) nxt[i] = g_hp[hb + i*96];
        }
        int ib = (bk*NCH + c)*8*96 + d;
        #pragma unroll
        for (int n = 0; n < 8; n++) g_hin[ib + n*96] = h[n];
        #pragma unroll
        for (int n = 0; n < 8; n++) h[n] = fmaf(cur[8+n], h[n], cur[n]);
        #pragma unroll
        for (int i = 0; i < 16; i++) cur[i] = nxt[i];
    }
}

// ---------------- K6: scan pass 2 (seeded recompute, emit y) ----------------
__global__ void __launch_bounds__(96) k_scan2(const float* __restrict__ alogs){
    __shared__ __align__(16) float bS[CS*8];
    __shared__ __align__(16) float cS[CS*8];
    int chunk = blockIdx.x, bk = blockIdx.y;
    int k = bk & 3;
    int d = threadIdx.x;
    int l0 = chunk*CS;
    for (int i = d; i < CS*8; i += 96){
        bS[i] = g_bB[(bk*LL + l0)*8 + i];
        cS[i] = g_bC[(bk*LL + l0)*8 + i];
    }
    float aN[8]; bool fast = true;
    const float* arow = alogs + (k*96 + d)*8;
    #pragma unroll
    for (int n = 0; n < 8; n++){
        float a = -__expf(arow[n]); aN[n] = a;
        fast = fast && (fabsf(a + (float)(n+1)) < 1e-3f*(float)(n+1));
    }
    float h[8];
    {
        int ib = (bk*NCH + chunk)*8*96 + d;
        #pragma unroll
        for (int n = 0; n < 8; n++) h[n] = g_hin[ib + n*96];
    }
    __syncthreads();
    int base2 = ((bk*NCH + chunk)*96 + d)*CS;
    int ybase = (bk*LL + l0)*96 + d;
    if (fast){
        const float4* eu4 = (const float4*)(g_eu + base2);
        float4 buf[4];
        #pragma unroll
        for (int i = 0; i < 4; i++) buf[i] = eu4[i];
        for (int grp = 0; grp < NGRP; grp++){
            float4 nxt[4];
            if (grp + 1 < NGRP){
                #pragma unroll
                for (int i = 0; i < 4; i++) nxt[i] = eu4[(grp+1)*4 + i];
            }
            #pragma unroll
            for (int i = 0; i < 4; i++){
                int s = grp*8 + i*2;
                {   float e1 = buf[i].x, u = buf[i].y;
                    float P[8]; POWER_TREE(e1, P);
                    float4 b0 = *(const float4*)(bS + s*8);
                    float4 b1 = *(const float4*)(bS + s*8 + 4);
                    h[0]=fmaf(P[0],h[0],u*b0.x); h[1]=fmaf(P[1],h[1],u*b0.y);
                    h[2]=fmaf(P[2],h[2],u*b0.z); h[3]=fmaf(P[3],h[3],u*b0.w);
                    h[4]=fmaf(P[4],h[4],u*b1.x); h[5]=fmaf(P[5],h[5],u*b1.y);
                    h[6]=fmaf(P[6],h[6],u*b1.z); h[7]=fmaf(P[7],h[7],u*b1.w);
                    float4 c0 = *(const float4*)(cS + s*8);
                    float4 c1 = *(const float4*)(cS + s*8 + 4);
                    float a0 = h[0]*c0.x, a1 = h[1]*c0.y;
                    a0 = fmaf(h[2], c0.z, a0);  a1 = fmaf(h[3], c0.w, a1);
                    a0 = fmaf(h[4], c1.x, a0);  a1 = fmaf(h[5], c1.y, a1);
                    a0 = fmaf(h[6], c1.z, a0);  a1 = fmaf(h[7], c1.w, a1);
                    g_y[ybase + s*96] = a0 + a1;
                }
                {   float e1 = buf[i].z, u = buf[i].w;
                    float P[8]; POWER_TREE(e1, P);
                    float4 b0 = *(const float4*)(bS + (s+1)*8);
                    float4 b1 = *(const float4*)(bS + (s+1)*8 + 4);
                    h[0]=fmaf(P[0],h[0],u*b0.x); h[1]=fmaf(P[1],h[1],u*b0.y);
                    h[2]=fmaf(P[2],h[2],u*b0.z); h[3]=fmaf(P[3],h[3],u*b0.w);
                    h[4]=fmaf(P[4],h[4],u*b1.x); h[5]=fmaf(P[5],h[5],u*b1.y);
                    h[6]=fmaf(P[6],h[6],u*b1.z); h[7]=fmaf(P[7],h[7],u*b1.w);
                    float4 c0 = *(const float4*)(cS + (s+1)*8);
                    float4 c1 = *(const float4*)(cS + (s+1)*8 + 4);
                    float a0 = h[0]*c0.x, a1 = h[1]*c0.y;
                    a0 = fmaf(h[2], c0.z, a0);  a1 = fmaf(h[3], c0.w, a1);
                    a0 = fmaf(h[4], c1.x, a0);  a1 = fmaf(h[5], c1.y, a1);
                    a0 = fmaf(h[6], c1.z, a0);  a1 = fmaf(h[7], c1.w, a1);
                    g_y[ybase + (s+1)*96] = a0 + a1;
                }
            }
            #pragma unroll
            for (int i = 0; i < 4; i++) buf[i] = nxt[i];
        }
    } else {
        const float2* eu2 = g_eu + base2;
        for (int s = 0; s < CS; s++){
            float2 eu = eu2[s];
            float delta = -__logf(fmaxf(eu.x, 1e-37f));
            float acc = 0.f;
            #pragma unroll
            for (int n = 0; n < 8; n++){
                float dA = __expf(delta*aN[n]);
                h[n] = fmaf(dA, h[n], eu.y*bS[s*8 + n]);
                acc  = fmaf(h[n], cS[s*8 + n], acc);
            }
            g_y[ybase + s*96] = acc;
        }
    }
}

// ---------------- K7: merge 4 directions + Ds*x + LN + gate + out-proj ----------------
// grid 256 (= B * 64 rows), block 192, dynamic smem. Writes planar (b,c,p).
__global__ void __launch_bounds__(192) k_out(const float* __restrict__ Ds,
                      const float* __restrict__ lng,
                      const float* __restrict__ lnb, const float* __restrict__ ow,
                      float* __restrict__ dst){
    extern __shared__ __align__(16) float dyn[];
    float* yoT   = dyn;                 // 96*68 : [d][m]
    float* wS    = dyn + 96*68;         // 96*97
    float* meanS = wS + 96*97;          // 64
    float* rstdS = meanS + 64;          // 64
    float* dsS   = rstdS + 64;          // 96
    float* lgS   = dsS + 96;            // 96
    float* lbS   = lgS + 96;            // 96
    int t  = threadIdx.x;
    int b  = blockIdx.x >> 6;
    int p0 = (blockIdx.x & 63) << 6;
    for (int i = t; i < 96*96; i += 192){
        int c = i / 96, d = i - c*96;
        wS[c*97 + d] = ow[i];
    }
    if (t < 96){
        dsS[t] = Ds[t] + Ds[96 + t] + Ds[192 + t] + Ds[288 + t];
        lgS[t] = lng[t];
        lbS[t] = lnb[t];
    }
    __syncthreads();
    for (int i = t; i < 6144; i += 192){
        int d = i % 96, m = i / 96;
        int p  = p0 + m;
        int pt = ((p & 63) << 6) | (p >> 6);
        float v = g_y[((b*4 + 0)*LL + p)*96 + d]
                + g_y[((b*4 + 1)*LL + pt)*96 + d]
                + g_y[((b*4 + 2)*LL + (4095 - p))*96 + d]
                + g_y[((b*4 + 3)*LL + (4095 - pt))*96 + d]
                + dsS[d] * g_xc[(b*LL + p)*96 + d];
        yoT[d*68 + m] = v;
    }
    __syncthreads();
    if (t < 64){
        float s = 0.f, s2 = 0.f;
        for (int d = 0; d < 96; d++){ float v = yoT[d*68 + t]; s += v; s2 = fmaf(v, v, s2); }
        float mean = s * (1.f/96.f);
        float var  = s2 * (1.f/96.f) - mean*mean;
        meanS[t] = mean;
        rstdS[t] = rsqrtf(var + 1e-5f);
    }
    __syncthreads();
    for (int i = t; i < 6144; i += 192){
        int d = i % 96, m = i / 96;
        float v = (yoT[d*68 + m] - meanS[m]) * rstdS[m] * lgS[d] + lbS[d];
        v *= g_z[(b*LL + p0 + m)*96 + d];
        yoT[d*68 + m] = v;
    }
    __syncthreads();
    {
        int c = t % 96, half = t / 96;
        int m0 = half*32;
        float acc[32];
        #pragma unroll
        for (int m = 0; m < 32; m++) acc[m] = 0.f;
        const float* wrow = wS + c*97;
        for (int d = 0; d < 96; d++){
            float wv = wrow[d];
            const float4* yr = (const float4*)(yoT + d*68 + m0);
            #pragma unroll
            for (int m4 = 0; m4 < 8; m4++){
                float4 yv = yr[m4];
                acc[4*m4+0] = fmaf(wv, yv.x, acc[4*m4+0]);
                acc[4*m4+1] = fmaf(wv, yv.y, acc[4*m4+1]);
                acc[4*m4+2] = fmaf(wv, yv.z, acc[4*m4+2]);
                acc[4*m4+3] = fmaf(wv, yv.w, acc[4*m4+3]);
            }
        }
        float* orow = dst + (b*96 + c)*LL + p0 + m0;
        #pragma unroll
        for (int m = 0; m < 32; m++) orow[m] = acc[m];
    }
}

// ---------------- launcher ----------------
extern "C" void kernel_launch(void* const* d_in, const int* in_sizes, int n_in,
                              void* d_out, int out_size){
    (void)in_sizes; (void)n_in; (void)out_size;
    const int SM_INPROJ = (64*97 + 192*97) * 4;                    // 99328 B
    const int SM_OUT    = (96*68 + 96*97 + 128 + 3*96) * 4;        // 65536 B
    cudaFuncSetAttribute(k_inproj, cudaFuncAttributeMaxDynamicSharedMemorySize, SM_INPROJ);
    cudaFuncSetAttribute(k_out,    cudaFuncAttributeMaxDynamicSharedMemorySize, SM_OUT);
    const float* input = (const float*)d_in[0];
    void* midp = nullptr;
    cudaGetSymbolAddress(&midp, g_mid);
    for (int blk = 0; blk < 2; blk++){
        const float* W[11];
        for (int i = 0; i < 11; i++) W[i] = (const float*)d_in[1 + blk*11 + i];
        const float* src = (blk == 0) ? input : (const float*)midp;
        float* dst = (blk == 0) ? (float*)midp : (float*)d_out;
        k_inproj<<<256, 192, SM_INPROJ>>>(src, W[0]);
        k_conv  <<<6144, 256>>>(W[1], W[2]);
        k_xproj <<<1024, 256>>>(W[3], W[4], W[5]);
        k_scan1 <<<dim3(NCH, 16), 96>>>(W[6]);
        k_mid   <<<12, 128>>>();
        k_scan2 <<<dim3(NCH, 16), 96>>>(W[6]);
        k_out   <<<256, 192, SM_OUT>>>(W[7], W[8], W[9], W[10], dst);
    }
}

// round 13
// speedup vs baseline: 1.6806x; 1.0004x over previous
#include <cuda_runtime.h>

#define BATCH 4
#define DD 96
#define NS 8
#define KD 4
#define LL 4096
#define CS 64     // chunk size (steps)
#define NCH 64    // number of chunks = LL/CS
#define NGRP 8    // CS/8

// ---------------- scratch (device globals; no allocation allowed) ----------------
__device__ float  g_xa [BATCH*LL*DD];
__device__ float  g_z  [BATCH*LL*DD];          // silu(z)
__device__ float  g_xc [BATCH*LL*DD];          // conv+silu output
__device__ float2 g_eu [BATCH*KD*LL*DD];       // {e1,u} ; layout [(bk*NCH+ch)*96+d]*CS + s
__device__ float  g_bB [BATCH*KD*LL*8];        // B
__device__ float  g_bC [BATCH*KD*LL*8];        // C
__device__ float  g_y  [BATCH*KD*LL*DD];       // scan output per direction
__device__ float  g_hp [BATCH*KD*NCH*16*DD];   // per-chunk {h_end(8),P(8)} comp-major [..][comp][d]
__device__ float  g_hin[BATCH*KD*NCH*8*DD];    // per-chunk incoming state comp-major
__device__ float  g_mid[BATCH*DD*LL];          // inter-block activation, planar (b,c,p)

// ---------------- K1: in-projection GEMM (planar (b,c,p) -> xa, silu(z)) --------
// grid 256 (= B * L/64), block 192, dynamic smem.
__global__ void __launch_bounds__(192) k_inproj(const float* __restrict__ src,
                                                const float* __restrict__ in_w){
    extern __shared__ __align__(16) float dyn[];
    float* sm = dyn;              // 64*97 : X[96][64] then OUT[64][97]
    float* wS = dyn + 64*97;      // 192*97
    int b  = blockIdx.x >> 6;
    int p0 = (blockIdx.x & 63) << 6;
    int t  = threadIdx.x;
    for (int i = t; i < 96*64; i += 192){
        int c = i >> 6, m = i & 63;
        sm[i] = src[((b*96 + c) << 12) + p0 + m];
    }
    for (int i = t; i < 192*96; i += 192){
        int row = i / 96, col = i - row*96;
        wS[row*97 + col] = in_w[i];
    }
    __syncthreads();
    float acc[64];
    #pragma unroll
    for (int m = 0; m < 64; m++) acc[m] = 0.f;
    const float* wrow = wS + t*97;
    for (int c = 0; c < 96; c++){
        float wv = wrow[c];
        const float4* xr = (const float4*)(sm + (c<<6));
        #pragma unroll
        for (int m4 = 0; m4 < 16; m4++){
            float4 xv = xr[m4];
            acc[4*m4+0] = fmaf(wv, xv.x, acc[4*m4+0]);
            acc[4*m4+1] = fmaf(wv, xv.y, acc[4*m4+1]);
            acc[4*m4+2] = fmaf(wv, xv.z, acc[4*m4+2]);
            acc[4*m4+3] = fmaf(wv, xv.w, acc[4*m4+3]);
        }
    }
    __syncthreads();
    if (t < 96){
        #pragma unroll
        for (int m = 0; m < 64; m++) sm[m*97 + t] = acc[m];
    }
    __syncthreads();
    for (int i = t; i < 64*96; i += 192){
        int m = i/96, d = i - m*96;
        g_xa[(b*LL + p0 + m)*96 + d] = sm[m*97 + d];
    }
    __syncthreads();
    if (t >= 96){
        #pragma unroll
        for (int m = 0; m < 64; m++) sm[m*97 + (t-96)] = acc[m];
    }
    __syncthreads();
    for (int i = t; i < 64*96; i += 192){
        int m = i/96, d = i - m*96;
        float v = sm[m*97 + d];
        g_z[(b*LL + p0 + m)*96 + d] = v * __fdividef(1.f, 1.f + __expf(-v));
    }
}

// ---------------- K2: depthwise 3x3 conv + bias + silu ----------------
// grid 6144, block 256 : one thread per (b,p,d)
__global__ void k_conv(const float* __restrict__ cw, const float* __restrict__ cb){
    int idx = blockIdx.x*256 + threadIdx.x;
    int d  = idx % 96;
    int pp = idx / 96;
    int p  = pp & 4095, b = pp >> 12;
    int h  = p >> 6,    w = p & 63;
    const float* wt = cw + d*9;
    float a = 0.f;
    #pragma unroll
    for (int i = 0; i < 3; i++){
        int hh = h + i - 1;
        if ((unsigned)hh < 64u){
            #pragma unroll
            for (int j = 0; j < 3; j++){
                int ww = w + j - 1;
                if ((unsigned)ww < 64u)
                    a = fmaf(__ldg(wt + i*3 + j), g_xa[(b*LL + (hh<<6) + ww)*96 + d], a);
            }
        }
    }
    a += __ldg(cb + d);
    g_xc[idx] = a * __fdividef(1.f, 1.f + __expf(-a));
}

// direction index map: scan step l of direction k reads spatial position perm(k,l)
__device__ __forceinline__ int perm_idx(int k, int l){
    if (k == 0) return l;
    if (k == 1) return ((l & 63) << 6) | (l >> 6);
    if (k == 2) return 4095 - l;
    int m = 4095 - l; return ((m & 63) << 6) | (m >> 6);
}

// ---------------- K3: x-projection + dt + softplus precompute ----------------
// grid 1024 (= B*K * NCH), block 256. 64 positions (= one chunk) per CTA.
// xvT [d][m] pad 65 -> conflict-free; warp-uniform channels -> broadcast xpS.
__global__ void __launch_bounds__(256) k_xproj(const float* __restrict__ xpw,
                        const float* __restrict__ dtw, const float* __restrict__ dtb){
    __shared__ float xvT[96*65];       // [d][m] 24.96 KB
    __shared__ float xdbl[64*25];
    __shared__ float xpS[22*96];
    __shared__ float dtwS[96*6];
    __shared__ float dtbS[96];
    int t   = threadIdx.x;
    int g   = blockIdx.x;
    int seg = g & 63, bk = g >> 6;     // seg == chunk
    int b   = bk >> 2,  k = bk & 3;
    int l0  = seg << 6;
    for (int i = t; i < 22*96; i += 256) xpS[i]  = xpw[k*22*96 + i];
    for (int i = t; i < 96*6;  i += 256) dtwS[i] = dtw[k*96*6 + i];
    if (t < 96) dtbS[t] = dtb[k*96 + t];
    for (int i = t; i < 64*96; i += 256){
        int m = i/96, d = i - m*96;
        int p = perm_idx(k, l0 + m);
        xvT[d*65 + m] = g_xc[(b*LL + p)*96 + d];
    }
    __syncthreads();
    // GEMM: 22 channels x 64 positions. lane = m (conflict-free), warp-uniform c (broadcast).
    {
        int m  = t & 63;
        int c0 = t >> 6;               // 0..3
        float a[6];
        #pragma unroll
        for (int j = 0; j < 6; j++) a[j] = 0.f;
        #pragma unroll 2
        for (int d = 0; d < 96; d++){
            float xv = xvT[d*65 + m];
            const float* xpd = xpS + d;
            #pragma unroll
            for (int j = 0; j < 6; j++){
                int c = c0 + 4*j;
                if (c < 22) a[j] = fmaf(xpd[c*96], xv, a[j]);
            }
        }
        #pragma unroll
        for (int j = 0; j < 6; j++){
            int c = c0 + 4*j;
            if (c < 22) xdbl[m*25 + c] = a[j];
        }
    }
    __syncthreads();
    for (int j = t; j < 64*96; j += 256){
        int m = j & 63, d = j >> 6;        // m fastest -> contiguous stores
        float s = dtbS[d];
        #pragma unroll
        for (int r = 0; r < 6; r++) s = fmaf(dtwS[d*6 + r], xdbl[m*25 + r], s);
        float et    = __expf(fminf(s, 60.f));
        float delta = (s > 15.f) ? s : __logf(1.f + et);   // softplus
        float e1    = __fdividef(1.f, 1.f + et);           // exp(-softplus(s))
        g_eu[((bk*NCH + seg)*96 + d)*CS + m] = make_float2(e1, delta * xvT[d*65 + m]);
    }
    for (int j = t; j < 64*8; j += 256){
        int m = j >> 3, i = j & 7;
        g_bB[(bk*LL + l0 + m)*8 + i] = xdbl[m*25 + 6 + i];
        g_bC[(bk*LL + l0 + m)*8 + i] = xdbl[m*25 + 14 + i];
    }
}

// log-depth powers e1^1..e1^8
#define POWER_TREE(e1, P)                                     \
    { P[0]=e1; P[1]=e1*e1; P[3]=P[1]*P[1]; P[2]=P[1]*e1;      \
      P[4]=P[3]*e1; P[5]=P[3]*P[1]; P[6]=P[3]*P[2]; P[7]=P[3]*P[3]; }

// ---------------- K4: scan pass 1 (per-chunk h_end and A-product) ----------------
// grid (NCH, 16), block 96
__global__ void __launch_bounds__(96) k_scan1(const float* __restrict__ alogs){
    __shared__ __align__(16) float bS[CS*8];
    int chunk = blockIdx.x, bk = blockIdx.y;
    int k = bk & 3;
    int d = threadIdx.x;
    int l0 = chunk*CS;
    for (int i = d; i < CS*8; i += 96) bS[i] = g_bB[(bk*LL + l0)*8 + i];
    float aN[8]; bool fast = true;
    const float* arow = alogs + (k*96 + d)*8;
    #pragma unroll
    for (int n = 0; n < 8; n++){
        float a = -__expf(arow[n]); aN[n] = a;
        fast = fast && (fabsf(a + (float)(n+1)) < 1e-3f*(float)(n+1));
    }
    __syncthreads();
    float h[8];
    #pragma unroll
    for (int n = 0; n < 8; n++) h[n] = 0.f;
    int base2 = ((bk*NCH + chunk)*96 + d)*CS;
    int ob = (bk*NCH + chunk)*16*96 + d;    // comp-major: +comp*96
    if (fast){
        const float4* eu4 = (const float4*)(g_eu + base2);  // 2 steps per float4
        float4 buf[4];
        #pragma unroll
        for (int i = 0; i < 4; i++) buf[i] = eu4[i];
        float q = 1.f;
        for (int grp = 0; grp < NGRP; grp++){
            float4 nxt[4];
            if (grp + 1 < NGRP){
                #pragma unroll
                for (int i = 0; i < 4; i++) nxt[i] = eu4[(grp+1)*4 + i];
            }
            #pragma unroll
            for (int i = 0; i < 4; i++){
                int s = grp*8 + i*2;
                {   float e1 = buf[i].x, u = buf[i].y;
                    float P[8]; POWER_TREE(e1, P);
                    q *= e1;
                    float4 b0 = *(const float4*)(bS + s*8);
                    float4 b1 = *(const float4*)(bS + s*8 + 4);
                    h[0]=fmaf(P[0],h[0],u*b0.x); h[1]=fmaf(P[1],h[1],u*b0.y);
                    h[2]=fmaf(P[2],h[2],u*b0.z); h[3]=fmaf(P[3],h[3],u*b0.w);
                    h[4]=fmaf(P[4],h[4],u*b1.x); h[5]=fmaf(P[5],h[5],u*b1.y);
                    h[6]=fmaf(P[6],h[6],u*b1.z); h[7]=fmaf(P[7],h[7],u*b1.w);
                }
                {   float e1 = buf[i].z, u = buf[i].w;
                    float P[8]; POWER_TREE(e1, P);
                    q *= e1;
                    float4 b0 = *(const float4*)(bS + (s+1)*8);
                    float4 b1 = *(const float4*)(bS + (s+1)*8 + 4);
                    h[0]=fmaf(P[0],h[0],u*b0.x); h[1]=fmaf(P[1],h[1],u*b0.y);
                    h[2]=fmaf(P[2],h[2],u*b0.z); h[3]=fmaf(P[3],h[3],u*b0.w);
                    h[4]=fmaf(P[4],h[4],u*b1.x); h[5]=fmaf(P[5],h[5],u*b1.y);
                    h[6]=fmaf(P[6],h[6],u*b1.z); h[7]=fmaf(P[7],h[7],u*b1.w);
                }
            }
            #pragma unroll
            for (int i = 0; i < 4; i++) buf[i] = nxt[i];
        }
        float P[8]; POWER_TREE(q, P);
        #pragma unroll
        for (int n = 0; n < 8; n++){ g_hp[ob + n*96] = h[n]; g_hp[ob + (8+n)*96] = P[n]; }
    } else {
        const float2* eu2 = g_eu + base2;
        float P[8];
        #pragma unroll
        for (int n = 0; n < 8; n++) P[n] = 1.f;
        for (int s = 0; s < CS; s++){
            float2 eu = eu2[s];
            float delta = -__logf(fmaxf(eu.x, 1e-37f));
            #pragma unroll
            for (int n = 0; n < 8; n++){
                float dA = __expf(delta*aN[n]);
                h[n] = fmaf(dA, h[n], eu.y*bS[s*8 + n]);
                P[n] *= dA;
            }
        }
        #pragma unroll
        for (int n = 0; n < 8; n++){ g_hp[ob + n*96] = h[n]; g_hp[ob + (8+n)*96] = P[n]; }
    }
}

// ---------------- K5: chunk-boundary scan (tiny, coalesced + prefetched) ----------------
__global__ void k_mid(){
    int t = blockIdx.x*128 + threadIdx.x;
    if (t >= 16*96) return;
    int bk = t/96, d = t - bk*96;
    float h[8];
    #pragma unroll
    for (int n = 0; n < 8; n++) h[n] = 0.f;
    float cur[16];
    {
        int hb = (bk*NCH)*16*96 + d;
        #pragma unroll
        for (int i = 0; i < 16; i++) cur[i] = g_hp[hb + i*96];
    }
    for (int c = 0; c < NCH; c++){
        float nxt[16];
        if (c + 1 < NCH){
            int hb = (bk*NCH + c + 1)*16*96 + d;
            #pragma unroll
            for (int i = 0; i < 16; i++) nxt[i] = g_hp[hb + i*96];
        }
        int ib = (bk*NCH + c)*8*96 + d;
        #pragma unroll
        for (int n = 0; n < 8; n++) g_hin[ib + n*96] = h[n];
        #pragma unroll
        for (int n = 0; n < 8; n++) h[n] = fmaf(cur[8+n], h[n], cur[n]);
        #pragma unroll
        for (int i = 0; i < 16; i++) cur[i] = nxt[i];
    }
}

// ---------------- K6: scan pass 2 (seeded recompute, emit y) ----------------
__global__ void __launch_bounds__(96) k_scan2(const float* __restrict__ alogs){
    __shared__ __align__(16) float bS[CS*8];
    __shared__ __align__(16) float cS[CS*8];
    int chunk = blockIdx.x, bk = blockIdx.y;
    int k = bk & 3;
    int d = threadIdx.x;
    int l0 = chunk*CS;
    for (int i = d; i < CS*8; i += 96){
        bS[i] = g_bB[(bk*LL + l0)*8 + i];
        cS[i] = g_bC[(bk*LL + l0)*8 + i];
    }
    float aN[8]; bool fast = true;
    const float* arow = alogs + (k*96 + d)*8;
    #pragma unroll
    for (int n = 0; n < 8; n++){
        float a = -__expf(arow[n]); aN[n] = a;
        fast = fast && (fabsf(a + (float)(n+1)) < 1e-3f*(float)(n+1));
    }
    float h[8];
    {
        int ib = (bk*NCH + chunk)*8*96 + d;
        #pragma unroll
        for (int n = 0; n < 8; n++) h[n] = g_hin[ib + n*96];
    }
    __syncthreads();
    int base2 = ((bk*NCH + chunk)*96 + d)*CS;
    int ybase = (bk*LL + l0)*96 + d;
    if (fast){
        const float4* eu4 = (const float4*)(g_eu + base2);
        float4 buf[4];
        #pragma unroll
        for (int i = 0; i < 4; i++) buf[i] = eu4[i];
        for (int grp = 0; grp < NGRP; grp++){
            float4 nxt[4];
            if (grp + 1 < NGRP){
                #pragma unroll
                for (int i = 0; i < 4; i++) nxt[i] = eu4[(grp+1)*4 + i];
            }
            #pragma unroll
            for (int i = 0; i < 4; i++){
                int s = grp*8 + i*2;
                {   float e1 = buf[i].x, u = buf[i].y;
                    float P[8]; POWER_TREE(e1, P);
                    float4 b0 = *(const float4*)(bS + s*8);
                    float4 b1 = *(const float4*)(bS + s*8 + 4);
                    h[0]=fmaf(P[0],h[0],u*b0.x); h[1]=fmaf(P[1],h[1],u*b0.y);
                    h[2]=fmaf(P[2],h[2],u*b0.z); h[3]=fmaf(P[3],h[3],u*b0.w);
                    h[4]=fmaf(P[4],h[4],u*b1.x); h[5]=fmaf(P[5],h[5],u*b1.y);
                    h[6]=fmaf(P[6],h[6],u*b1.z); h[7]=fmaf(P[7],h[7],u*b1.w);
                    float4 c0 = *(const float4*)(cS + s*8);
                    float4 c1 = *(const float4*)(cS + s*8 + 4);
                    float a0 = h[0]*c0.x, a1 = h[1]*c0.y;
                    a0 = fmaf(h[2], c0.z, a0);  a1 = fmaf(h[3], c0.w, a1);
                    a0 = fmaf(h[4], c1.x, a0);  a1 = fmaf(h[5], c1.y, a1);
                    a0 = fmaf(h[6], c1.z, a0);  a1 = fmaf(h[7], c1.w, a1);
                    g_y[ybase + s*96] = a0 + a1;
                }
                {   float e1 = buf[i].z, u = buf[i].w;
                    float P[8]; POWER_TREE(e1, P);
                    float4 b0 = *(const float4*)(bS + (s+1)*8);
                    float4 b1 = *(const float4*)(bS + (s+1)*8 + 4);
                    h[0]=fmaf(P[0],h[0],u*b0.x); h[1]=fmaf(P[1],h[1],u*b0.y);
                    h[2]=fmaf(P[2],h[2],u*b0.z); h[3]=fmaf(P[3],h[3],u*b0.w);
                    h[4]=fmaf(P[4],h[4],u*b1.x); h[5]=fmaf(P[5],h[5],u*b1.y);
                    h[6]=fmaf(P[6],h[6],u*b1.z); h[7]=fmaf(P[7],h[7],u*b1.w);
                    float4 c0 = *(const float4*)(cS + (s+1)*8);
                    float4 c1 = *(const float4*)(cS + (s+1)*8 + 4);
                    float a0 = h[0]*c0.x, a1 = h[1]*c0.y;
                    a0 = fmaf(h[2], c0.z, a0);  a1 = fmaf(h[3], c0.w, a1);
                    a0 = fmaf(h[4], c1.x, a0);  a1 = fmaf(h[5], c1.y, a1);
                    a0 = fmaf(h[6], c1.z, a0);  a1 = fmaf(h[7], c1.w, a1);
                    g_y[ybase + (s+1)*96] = a0 + a1;
                }
            }
            #pragma unroll
            for (int i = 0; i < 4; i++) buf[i] = nxt[i];
        }
    } else {
        const float2* eu2 = g_eu + base2;
        for (int s = 0; s < CS; s++){
            float2 eu = eu2[s];
            float delta = -__logf(fmaxf(eu.x, 1e-37f));
            float acc = 0.f;
            #pragma unroll
            for (int n = 0; n < 8; n++){
                float dA = __expf(delta*aN[n]);
                h[n] = fmaf(dA, h[n], eu.y*bS[s*8 + n]);
                acc  = fmaf(h[n], cS[s*8 + n], acc);
            }
            g_y[ybase + s*96] = acc;
        }
    }
}

// ---------------- K7: merge 4 directions + Ds*x + LN + gate + out-proj ----------------
// grid 256 (= B * 64 rows), block 192, dynamic smem. Writes planar (b,c,p).
__global__ void __launch_bounds__(192) k_out(const float* __restrict__ Ds,
                      const float* __restrict__ lng,
                      const float* __restrict__ lnb, const float* __restrict__ ow,
                      float* __restrict__ dst){
    extern __shared__ __align__(16) float dyn[];
    float* yoT   = dyn;                 // 96*68 : [d][m]
    float* wS    = dyn + 96*68;         // 96*97
    float* meanS = wS + 96*97;          // 64
    float* rstdS = meanS + 64;          // 64
    float* dsS   = rstdS + 64;          // 96
    float* lgS   = dsS + 96;            // 96
    float* lbS   = lgS + 96;            // 96
    int t  = threadIdx.x;
    int b  = blockIdx.x >> 6;
    int p0 = (blockIdx.x & 63) << 6;
    for (int i = t; i < 96*96; i += 192){
        int c = i / 96, d = i - c*96;
        wS[c*97 + d] = ow[i];
    }
    if (t < 96){
        dsS[t] = Ds[t] + Ds[96 + t] + Ds[192 + t] + Ds[288 + t];
        lgS[t] = lng[t];
        lbS[t] = lnb[t];
    }
    __syncthreads();
    for (int i = t; i < 6144; i += 192){
        int d = i % 96, m = i / 96;
        int p  = p0 + m;
        int pt = ((p & 63) << 6) | (p >> 6);
        float v = g_y[((b*4 + 0)*LL + p)*96 + d]
                + g_y[((b*4 + 1)*LL + pt)*96 + d]
                + g_y[((b*4 + 2)*LL + (4095 - p))*96 + d]
                + g_y[((b*4 + 3)*LL + (4095 - pt))*96 + d]
                + dsS[d] * g_xc[(b*LL + p)*96 + d];
        yoT[d*68 + m] = v;
    }
    __syncthreads();
    if (t < 64){
        float s = 0.f, s2 = 0.f;
        for (int d = 0; d < 96; d++){ float v = yoT[d*68 + t]; s += v; s2 = fmaf(v, v, s2); }
        float mean = s * (1.f/96.f);
        float var  = s2 * (1.f/96.f) - mean*mean;
        meanS[t] = mean;
        rstdS[t] = rsqrtf(var + 1e-5f);
    }
    __syncthreads();
    for (int i = t; i < 6144; i += 192){
        int d = i % 96, m = i / 96;
        float v = (yoT[d*68 + m] - meanS[m]) * rstdS[m] * lgS[d] + lbS[d];
        v *= g_z[(b*LL + p0 + m)*96 + d];
        yoT[d*68 + m] = v;
    }
    __syncthreads();
    {
        int c = t % 96, half = t / 96;
        int m0 = half*32;
        float acc[32];
        #pragma unroll
        for (int m = 0; m < 32; m++) acc[m] = 0.f;
        const float* wrow = wS + c*97;
        for (int d = 0; d < 96; d++){
            float wv = wrow[d];
            const float4* yr = (const float4*)(yoT + d*68 + m0);
            #pragma unroll
            for (int m4 = 0; m4 < 8; m4++){
                float4 yv = yr[m4];
                acc[4*m4+0] = fmaf(wv, yv.x, acc[4*m4+0]);
                acc[4*m4+1] = fmaf(wv, yv.y, acc[4*m4+1]);
                acc[4*m4+2] = fmaf(wv, yv.z, acc[4*m4+2]);
                acc[4*m4+3] = fmaf(wv, yv.w, acc[4*m4+3]);
            }
        }
        float* orow = dst + (b*96 + c)*LL + p0 + m0;
        #pragma unroll
        for (int m = 0; m < 32; m++) orow[m] = acc[m];
    }
}

// ---------------- launcher ----------------
extern "C" void kernel_launch(void* const* d_in, const int* in_sizes, int n_in,
                              void* d_out, int out_size){
    (void)in_sizes; (void)n_in; (void)out_size;
    const int SM_INPROJ = (64*97 + 192*97) * 4;                    // 99328 B
    const int SM_OUT    = (96*68 + 96*97 + 128 + 3*96) * 4;        // 65536 B
    cudaFuncSetAttribute(k_inproj, cudaFuncAttributeMaxDynamicSharedMemorySize, SM_INPROJ);
    cudaFuncSetAttribute(k_out,    cudaFuncAttributeMaxDynamicSharedMemorySize, SM_OUT);
    const float* input = (const float*)d_in[0];
    void* midp = nullptr;
    cudaGetSymbolAddress(&midp, g_mid);
    for (int blk = 0; blk < 2; blk++){
        const float* W[11];
        for (int i = 0; i < 11; i++) W[i] = (const float*)d_in[1 + blk*11 + i];
        const float* src = (blk == 0) ? input : (const float*)midp;
        float* dst = (blk == 0) ? (float*)midp : (float*)d_out;
        k_inproj<<<256, 192, SM_INPROJ>>>(src, W[0]);
        k_conv  <<<6144, 256>>>(W[1], W[2]);
        k_xproj <<<1024, 256>>>(W[3], W[4], W[5]);
        k_scan1 <<<dim3(NCH, 16), 96>>>(W[6]);
        k_mid   <<<12, 128>>>();
        k_scan2 <<<dim3(NCH, 16), 96>>>(W[6]);
        k_out   <<<256, 192, SM_OUT>>>(W[7], W[8], W[9], W[10], dst);
    }
}